// round 2
// baseline (speedup 1.0000x reference)
#include <cuda_runtime.h>

#define NB   12544   // 196 * 64
#define D    256
#define MEM  2048

// ---------------- scratch (device globals; no allocation allowed) ----------
__device__ float g_qc [NB * D];
__device__ float g_qf [NB * D];
__device__ float g_kc [MEM * D];
__device__ float g_kf [MEM * D];
__device__ float g_vcT[D * MEM];
__device__ float g_vfT[D * MEM];
__device__ float g_Sc [NB * MEM];
__device__ float g_Ss [NB * MEM];
__device__ float g_outc[NB * D];
__device__ float g_outs[NB * D];
__device__ float g_rsc[NB];
__device__ float g_rss[NB];
__device__ float g_qmean[NB];
__device__ float g_qvar [NB];
__device__ float g_kmean[MEM];
__device__ float g_kvar [MEM];

// ---------------------------------------------------------------------------
// NT GEMM: C[M,N] = A[M,K] @ B[N,K]^T     (row-major, lda = ldb = K, ldc = N)
// 64x64 block tile, 256 threads, 4x4 microtile, BK=16.
// MODE 0: plain   MODE 1: exp(acc/16)   MODE 2: SSIM -> exp
// ---------------------------------------------------------------------------
template <int MODE>
__global__ void gemm_nt(const float* __restrict__ A,
                        const float* __restrict__ B,
                        float* __restrict__ C,
                        int K, int Ncols,
                        const float* __restrict__ qmean,
                        const float* __restrict__ qvar,
                        const float* __restrict__ kmean,
                        const float* __restrict__ kvar)
{
    __shared__ float As[16][64];
    __shared__ float Bs[16][64];

    const int m0 = blockIdx.y * 64;
    const int n0 = blockIdx.x * 64;
    const int t  = threadIdx.x;
    const int tx = t & 15;          // 0..15  -> 4 output cols
    const int ty = t >> 4;          // 0..15  -> 4 output rows
    // load mapping: conflict-free STS (warp = 32 consecutive rows, fixed k-offset)
    const int lr = t & 63;          // tile row 0..63
    const int lk = (t >> 6) * 4;    // k-offset {0,4,8,12}

    float acc[4][4] = {};

    for (int k0 = 0; k0 < K; k0 += 16) {
        const float4 a4 = *(const float4*)&A[(size_t)(m0 + lr) * K + k0 + lk];
        const float4 b4 = *(const float4*)&B[(size_t)(n0 + lr) * K + k0 + lk];
        __syncthreads();
        As[lk + 0][lr] = a4.x; As[lk + 1][lr] = a4.y;
        As[lk + 2][lr] = a4.z; As[lk + 3][lr] = a4.w;
        Bs[lk + 0][lr] = b4.x; Bs[lk + 1][lr] = b4.y;
        Bs[lk + 2][lr] = b4.z; Bs[lk + 3][lr] = b4.w;
        __syncthreads();

        #pragma unroll
        for (int kk = 0; kk < 16; kk++) {
            const float4 a = *(const float4*)&As[kk][ty * 4];
            const float4 b = *(const float4*)&Bs[kk][tx * 4];
            const float av[4] = {a.x, a.y, a.z, a.w};
            const float bv[4] = {b.x, b.y, b.z, b.w};
            #pragma unroll
            for (int i = 0; i < 4; i++)
                #pragma unroll
                for (int j = 0; j < 4; j++)
                    acc[i][j] += av[i] * bv[j];
        }
    }

    #pragma unroll
    for (int i = 0; i < 4; i++) {
        const int row = m0 + ty * 4 + i;
        #pragma unroll
        for (int j = 0; j < 4; j++) {
            const int col = n0 + tx * 4 + j;
            float v = acc[i][j];
            if (MODE == 1) {
                v = __expf(v * 0.0625f);                 // 1/sqrt(256)
            } else if (MODE == 2) {
                const float qm = qmean[row];
                const float km = kmean[col];
                const float cov = (v - 256.0f * qm * km) * (1.0f / 255.0f);
                const float mp  = qm * km;
                const float num = (2.0f * mp + 0.01f) * (2.0f * cov + 0.03f);
                const float den = (qm * qm + km * km + 0.01f)
                                * (qvar[row] + kvar[col] + 0.03f);
                v = __expf(num / (den + 1e-8f));
            }
            C[(size_t)row * Ncols + col] = v;
        }
    }
}

// ---------------------------------------------------------------------------
// Per-row mean & unbiased variance over 256 columns. One block per row.
// ---------------------------------------------------------------------------
__global__ void row_stats(const float* __restrict__ X,
                          float* __restrict__ mean,
                          float* __restrict__ var)
{
    const int row = blockIdx.x;
    const float v = X[(size_t)row * 256 + threadIdx.x];
    float s = v, q = v * v;
    #pragma unroll
    for (int o = 16; o > 0; o >>= 1) {
        s += __shfl_xor_sync(0xFFFFFFFFu, s, o);
        q += __shfl_xor_sync(0xFFFFFFFFu, q, o);
    }
    __shared__ float ssum[8], ssq[8];
    const int w = threadIdx.x >> 5;
    if ((threadIdx.x & 31) == 0) { ssum[w] = s; ssq[w] = q; }
    __syncthreads();
    if (threadIdx.x == 0) {
        float S = 0.f, Q = 0.f;
        #pragma unroll
        for (int i = 0; i < 8; i++) { S += ssum[i]; Q += ssq[i]; }
        const float m = S * (1.0f / 256.0f);
        mean[row] = m;
        var[row]  = (Q - 256.0f * m * m) * (1.0f / 255.0f);
    }
}

// ---------------------------------------------------------------------------
// Row sums of exp-score matrix [*, MEM]. One block per row.
// ---------------------------------------------------------------------------
__global__ void row_sum(const float* __restrict__ S, float* __restrict__ rs)
{
    const int row = blockIdx.x;
    const float* p = S + (size_t)row * MEM;
    float s = 0.f;
    for (int c = threadIdx.x; c < MEM; c += 256) s += p[c];
    #pragma unroll
    for (int o = 16; o > 0; o >>= 1) s += __shfl_xor_sync(0xFFFFFFFFu, s, o);
    __shared__ float ssum[8];
    const int w = threadIdx.x >> 5;
    if ((threadIdx.x & 31) == 0) ssum[w] = s;
    __syncthreads();
    if (threadIdx.x == 0) {
        float S2 = 0.f;
        #pragma unroll
        for (int i = 0; i < 8; i++) S2 += ssum[i];
        rs[row] = S2;
    }
}

// ---------------------------------------------------------------------------
// Final: out = outc/rsc + outs/rss. One block (256 thr) per token row.
// ---------------------------------------------------------------------------
__global__ void combine(const float* __restrict__ outc,
                        const float* __restrict__ outs,
                        const float* __restrict__ rsc,
                        const float* __restrict__ rss,
                        float* __restrict__ out)
{
    const int row = blockIdx.x;
    const size_t idx = (size_t)row * 256 + threadIdx.x;
    out[idx] = outc[idx] * (1.0f / rsc[row]) + outs[idx] * (1.0f / rss[row]);
}

// ---------------------------------------------------------------------------
extern "C" void kernel_launch(void* const* d_in, const int* in_sizes, int n_in,
                              void* d_out, int out_size)
{
    const float* x     = (const float*)d_in[0];  // [196,64,256] -> [NB,D]
    const float* chmem = (const float*)d_in[1];  // [MEM,D]
    const float* chwq  = (const float*)d_in[2];
    const float* chwk  = (const float*)d_in[3];
    const float* chwv  = (const float*)d_in[4];
    const float* spmem = (const float*)d_in[5];  // [MEM,16,16] -> [MEM,256]
    const float* spwq  = (const float*)d_in[6];
    const float* spwk  = (const float*)d_in[7];
    const float* spwv  = (const float*)d_in[8];
    float* out = (float*)d_out;

    float *qc, *qf, *kc, *kf, *vcT, *vfT, *Sc, *Ss, *outc, *outs;
    float *rsc, *rss, *qm, *qv, *km, *kv;
    cudaGetSymbolAddress((void**)&qc,   g_qc);
    cudaGetSymbolAddress((void**)&qf,   g_qf);
    cudaGetSymbolAddress((void**)&kc,   g_kc);
    cudaGetSymbolAddress((void**)&kf,   g_kf);
    cudaGetSymbolAddress((void**)&vcT,  g_vcT);
    cudaGetSymbolAddress((void**)&vfT,  g_vfT);
    cudaGetSymbolAddress((void**)&Sc,   g_Sc);
    cudaGetSymbolAddress((void**)&Ss,   g_Ss);
    cudaGetSymbolAddress((void**)&outc, g_outc);
    cudaGetSymbolAddress((void**)&outs, g_outs);
    cudaGetSymbolAddress((void**)&rsc,  g_rsc);
    cudaGetSymbolAddress((void**)&rss,  g_rss);
    cudaGetSymbolAddress((void**)&qm,   g_qmean);
    cudaGetSymbolAddress((void**)&qv,   g_qvar);
    cudaGetSymbolAddress((void**)&km,   g_kmean);
    cudaGetSymbolAddress((void**)&kv,   g_kvar);

    const dim3 blk(256);

    // ---- projections (all NT form) ----
    gemm_nt<0><<<dim3(D / 64, NB / 64), blk>>>(x,     chwq,  qc,  D, D,
                                               nullptr, nullptr, nullptr, nullptr);
    gemm_nt<0><<<dim3(D / 64, NB / 64), blk>>>(x,     spwq,  qf,  D, D,
                                               nullptr, nullptr, nullptr, nullptr);
    gemm_nt<0><<<dim3(D / 64, MEM / 64), blk>>>(chmem, chwk, kc,  D, D,
                                               nullptr, nullptr, nullptr, nullptr);
    gemm_nt<0><<<dim3(D / 64, MEM / 64), blk>>>(spmem, spwk, kf,  D, D,
                                               nullptr, nullptr, nullptr, nullptr);
    // v^T[d,m] = sum_k W[d,k] * mem[m,k]  -> NT with A=W, B=mem
    gemm_nt<0><<<dim3(MEM / 64, D / 64), blk>>>(chwv, chmem, vcT, D, MEM,
                                               nullptr, nullptr, nullptr, nullptr);
    gemm_nt<0><<<dim3(MEM / 64, D / 64), blk>>>(spwv, spmem, vfT, D, MEM,
                                               nullptr, nullptr, nullptr, nullptr);

    // ---- SSIM row statistics ----
    row_stats<<<NB,  256>>>(qf, qm, qv);
    row_stats<<<MEM, 256>>>(kf, km, kv);

    // ---- score matrices with fused exp epilogue ----
    gemm_nt<1><<<dim3(MEM / 64, NB / 64), blk>>>(qc, kc, Sc, D, MEM,
                                                 nullptr, nullptr, nullptr, nullptr);
    gemm_nt<2><<<dim3(MEM / 64, NB / 64), blk>>>(qf, kf, Ss, D, MEM,
                                                 qm, qv, km, kv);

    // ---- softmax denominators ----
    row_sum<<<NB, 256>>>(Sc, rsc);
    row_sum<<<NB, 256>>>(Ss, rss);

    // ---- out = P @ V  (V stored transposed -> NT form, K = MEM) ----
    gemm_nt<0><<<dim3(D / 64, NB / 64), blk>>>(Sc, vcT, outc, MEM, D,
                                               nullptr, nullptr, nullptr, nullptr);
    gemm_nt<0><<<dim3(D / 64, NB / 64), blk>>>(Ss, vfT, outs, MEM, D,
                                               nullptr, nullptr, nullptr, nullptr);

    // ---- normalize and sum branches ----
    combine<<<NB, 256>>>(outc, outs, rsc, rss, out);
}

// round 5
// speedup vs baseline: 3.5349x; 3.5349x over previous
#include <cuda_runtime.h>
#include <cstdint>

#define NB   12544   // 196 * 64
#define D    256
#define MEM  2048

// ---------------- scratch (device globals; no allocation allowed) ----------
__device__ float g_xr [NB * D];      // tf32-rounded inputs
__device__ float g_cmr[MEM * D];
__device__ float g_smr[MEM * D];
__device__ float g_wqc[D * D];
__device__ float g_wkc[D * D];
__device__ float g_wvc[D * D];
__device__ float g_wqs[D * D];
__device__ float g_wks[D * D];
__device__ float g_wvs[D * D];

__device__ float g_qc [NB * D];
__device__ float g_qf [NB * D];
__device__ float g_kc [MEM * D];
__device__ float g_kf [MEM * D];
__device__ float g_vcT[D * MEM];
__device__ float g_vfT[D * MEM];
__device__ float g_Sc [NB * MEM];
__device__ float g_Ss [NB * MEM];
__device__ float g_outc[NB * D];
__device__ float g_outs[NB * D];
__device__ float g_rsc[NB];
__device__ float g_rss[NB];
__device__ float g_qmean[NB];
__device__ float g_qvar [NB];
__device__ float g_kmean[MEM];
__device__ float g_kvar [MEM];

// ---------------------------------------------------------------------------
__device__ __forceinline__ float rna_tf32(float x) {
    uint32_t u;
    asm("cvt.rna.tf32.f32 %0, %1;" : "=r"(u) : "f"(x));
    return __uint_as_float(u);
}

__device__ __forceinline__ void cpasync16(uint32_t smem, const void* gptr) {
    asm volatile("cp.async.cg.shared.global [%0], [%1], 16;\n"
                 :: "r"(smem), "l"(gptr));
}

__device__ __forceinline__ void mma_tf32(float* d, const uint32_t* a,
                                         const uint32_t* b) {
    asm volatile(
        "mma.sync.aligned.m16n8k8.row.col.f32.tf32.tf32.f32 "
        "{%0,%1,%2,%3},{%4,%5,%6,%7},{%8,%9},{%0,%1,%2,%3};"
        : "+f"(d[0]), "+f"(d[1]), "+f"(d[2]), "+f"(d[3])
        : "r"(a[0]), "r"(a[1]), "r"(a[2]), "r"(a[3]),
          "r"(b[0]), "r"(b[1]));
}

// ---------------------------------------------------------------------------
// TF32 tensor-core NT GEMM: C[M,N] = A[M,K] @ B[N,K]^T   (row-major, ld = K)
// 128x128 block tile, BK=32, 4 warps (64x64 per warp), 2-stage cp.async.
// M,N multiples of 128; K multiple of 32. Inputs must be tf32-pre-rounded.
// MODE 0: plain   MODE 1: exp(acc/16)   MODE 2: SSIM -> exp
// ROUND: 1 -> round result to tf32 on store (output feeds another GEMM)
// ---------------------------------------------------------------------------
#define SROW 36             // smem row stride in floats (pad 32 -> 36)
#define STILE (128 * SROW)  // floats per stage per matrix

template <int MODE, int ROUND>
__global__ void __launch_bounds__(128, 2)
gemm_tc(const float* __restrict__ A,
        const float* __restrict__ B,
        float* __restrict__ C,
        int K, int N,
        const float* __restrict__ qmean,
        const float* __restrict__ qvar,
        const float* __restrict__ kmean,
        const float* __restrict__ kvar)
{
    extern __shared__ float smem[];
    float* As = smem;               // [2][STILE]
    float* Bs = smem + 2 * STILE;   // [2][STILE]

    const int tid  = threadIdx.x;
    const int m0   = blockIdx.y * 128;
    const int n0   = blockIdx.x * 128;
    const int lane = tid & 31;
    const int wid  = tid >> 5;
    const int wm   = (wid & 1) * 64;
    const int wn   = (wid >> 1) * 64;
    const int gid  = lane >> 2;
    const int tig  = lane & 3;

    const uint32_t sA = (uint32_t)__cvta_generic_to_shared(As);
    const uint32_t sB = (uint32_t)__cvta_generic_to_shared(Bs);

    // load mapping: warp covers 4 rows x 8 chunks of 16B -> full 128B lines
    const int lrow = tid >> 3;      // 0..15, +16*i
    const int lch  = tid & 7;       // 16B chunk within 32-float row

    float acc[4][8][4] = {};

    const int KT = K >> 5;

    // stage loader (16 cp.async of 16B each + commit)
    auto load_stage = [&](int kt, int s) {
        const float* Ag = A + (size_t)(m0 + lrow) * K + kt * 32 + lch * 4;
        const float* Bg = B + (size_t)(n0 + lrow) * K + kt * 32 + lch * 4;
        uint32_t da = sA + (uint32_t)(s * STILE + lrow * SROW + lch * 4) * 4u;
        uint32_t db = sB + (uint32_t)(s * STILE + lrow * SROW + lch * 4) * 4u;
        #pragma unroll
        for (int i = 0; i < 8; i++) {
            cpasync16(da + (uint32_t)(i * 16 * SROW) * 4u, Ag + (size_t)i * 16 * K);
            cpasync16(db + (uint32_t)(i * 16 * SROW) * 4u, Bg + (size_t)i * 16 * K);
        }
        asm volatile("cp.async.commit_group;");
    };

    load_stage(0, 0);

    for (int kt = 0; kt < KT; kt++) {
        if (kt + 1 < KT) {
            load_stage(kt + 1, (kt + 1) & 1);
            asm volatile("cp.async.wait_group 1;");
        } else {
            asm volatile("cp.async.wait_group 0;");
        }
        __syncthreads();

        const float* as = As + (kt & 1) * STILE;
        const float* bs = Bs + (kt & 1) * STILE;

        #pragma unroll
        for (int k8 = 0; k8 < 4; k8++) {
            const int kk = k8 * 8 + tig;
            uint32_t af[4][4], bf[8][2];
            #pragma unroll
            for (int mt = 0; mt < 4; mt++) {
                const int r = wm + mt * 16 + gid;
                af[mt][0] = __float_as_uint(as[r * SROW + kk]);
                af[mt][1] = __float_as_uint(as[(r + 8) * SROW + kk]);
                af[mt][2] = __float_as_uint(as[r * SROW + kk + 4]);
                af[mt][3] = __float_as_uint(as[(r + 8) * SROW + kk + 4]);
            }
            #pragma unroll
            for (int nt = 0; nt < 8; nt++) {
                const int c = wn + nt * 8 + gid;
                bf[nt][0] = __float_as_uint(bs[c * SROW + kk]);
                bf[nt][1] = __float_as_uint(bs[c * SROW + kk + 4]);
            }
            #pragma unroll
            for (int mt = 0; mt < 4; mt++)
                #pragma unroll
                for (int nt = 0; nt < 8; nt++)
                    mma_tf32(acc[mt][nt], af[mt], bf[nt]);
        }
        __syncthreads();
    }

    // ------------------------------ epilogue -------------------------------
    float kmv[8][2], kvv[8][2];
    if (MODE == 2) {
        #pragma unroll
        for (int nt = 0; nt < 8; nt++) {
            const int c = n0 + wn + nt * 8 + 2 * tig;
            kmv[nt][0] = kmean[c];     kmv[nt][1] = kmean[c + 1];
            kvv[nt][0] = kvar[c];      kvv[nt][1] = kvar[c + 1];
        }
    }

    #pragma unroll
    for (int mt = 0; mt < 4; mt++) {
        #pragma unroll
        for (int half = 0; half < 2; half++) {
            const int r = m0 + wm + mt * 16 + gid + half * 8;
            float qm_ = 0.f, qv_ = 0.f;
            if (MODE == 2) { qm_ = qmean[r]; qv_ = qvar[r]; }
            #pragma unroll
            for (int nt = 0; nt < 8; nt++) {
                const int c = n0 + wn + nt * 8 + 2 * tig;
                float v0 = acc[mt][nt][half * 2 + 0];
                float v1 = acc[mt][nt][half * 2 + 1];
                if (MODE == 1) {
                    v0 = __expf(v0 * 0.0625f);
                    v1 = __expf(v1 * 0.0625f);
                } else if (MODE == 2) {
                    #pragma unroll
                    for (int j = 0; j < 2; j++) {
                        float& v = j ? v1 : v0;
                        const float km_ = kmv[nt][j];
                        const float kv_ = kvv[nt][j];
                        const float cov = (v - 256.0f * qm_ * km_) * (1.0f / 255.0f);
                        const float num = (2.0f * qm_ * km_ + 0.01f)
                                        * (2.0f * cov + 0.03f);
                        const float den = (qm_ * qm_ + km_ * km_ + 0.01f)
                                        * (qv_ + kv_ + 0.03f);
                        v = __expf(num / (den + 1e-8f));
                    }
                }
                if (ROUND) { v0 = rna_tf32(v0); v1 = rna_tf32(v1); }
                *(float2*)&C[(size_t)r * N + c] = make_float2(v0, v1);
            }
        }
    }
}

// ---------------------------------------------------------------------------
// elementwise tf32 RNA rounding
// ---------------------------------------------------------------------------
__global__ void round_tf32_kern(const float* __restrict__ in,
                                float* __restrict__ out, int n)
{
    const int i = blockIdx.x * 256 + threadIdx.x;
    if (i < n) out[i] = rna_tf32(in[i]);
}

// ---------------------------------------------------------------------------
// Per-row mean & unbiased variance over 256 columns. One block per row.
// ---------------------------------------------------------------------------
__global__ void row_stats(const float* __restrict__ X,
                          float* __restrict__ mean,
                          float* __restrict__ var)
{
    const int row = blockIdx.x;
    const float v = X[(size_t)row * 256 + threadIdx.x];
    float s = v, q = v * v;
    #pragma unroll
    for (int o = 16; o > 0; o >>= 1) {
        s += __shfl_xor_sync(0xFFFFFFFFu, s, o);
        q += __shfl_xor_sync(0xFFFFFFFFu, q, o);
    }
    __shared__ float ssum[8], ssq[8];
    const int w = threadIdx.x >> 5;
    if ((threadIdx.x & 31) == 0) { ssum[w] = s; ssq[w] = q; }
    __syncthreads();
    if (threadIdx.x == 0) {
        float S = 0.f, Q = 0.f;
        #pragma unroll
        for (int i = 0; i < 8; i++) { S += ssum[i]; Q += ssq[i]; }
        const float m = S * (1.0f / 256.0f);
        mean[row] = m;
        var[row]  = (Q - 256.0f * m * m) * (1.0f / 255.0f);
    }
}

// ---------------------------------------------------------------------------
__global__ void row_sum(const float* __restrict__ S, float* __restrict__ rs)
{
    const int row = blockIdx.x;
    const float* p = S + (size_t)row * MEM;
    float s = 0.f;
    for (int c = threadIdx.x; c < MEM; c += 256) s += p[c];
    #pragma unroll
    for (int o = 16; o > 0; o >>= 1) s += __shfl_xor_sync(0xFFFFFFFFu, s, o);
    __shared__ float ssum[8];
    const int w = threadIdx.x >> 5;
    if ((threadIdx.x & 31) == 0) ssum[w] = s;
    __syncthreads();
    if (threadIdx.x == 0) {
        float S2 = 0.f;
        #pragma unroll
        for (int i = 0; i < 8; i++) S2 += ssum[i];
        rs[row] = S2;
    }
}

// ---------------------------------------------------------------------------
__global__ void combine(const float* __restrict__ outc,
                        const float* __restrict__ outs,
                        const float* __restrict__ rsc,
                        const float* __restrict__ rss,
                        float* __restrict__ out)
{
    const int row = blockIdx.x;
    const size_t idx = (size_t)row * 256 + threadIdx.x;
    out[idx] = outc[idx] * (1.0f / rsc[row]) + outs[idx] * (1.0f / rss[row]);
}

// ---------------------------------------------------------------------------
static const int GEMM_SMEM = 4 * STILE * (int)sizeof(float);   // 73728 B

extern "C" void kernel_launch(void* const* d_in, const int* in_sizes, int n_in,
                              void* d_out, int out_size)
{
    const float* x     = (const float*)d_in[0];
    const float* chmem = (const float*)d_in[1];
    const float* chwq  = (const float*)d_in[2];
    const float* chwk  = (const float*)d_in[3];
    const float* chwv  = (const float*)d_in[4];
    const float* spmem = (const float*)d_in[5];
    const float* spwq  = (const float*)d_in[6];
    const float* spwk  = (const float*)d_in[7];
    const float* spwv  = (const float*)d_in[8];
    float* out = (float*)d_out;

    float *xr, *cmr, *smr, *wqc, *wkc, *wvc, *wqs, *wks, *wvs;
    float *qc, *qf, *kc, *kf, *vcT, *vfT, *Sc, *Ss, *outc, *outs;
    float *rsc, *rss, *qm, *qv, *km, *kv;
    cudaGetSymbolAddress((void**)&xr,   g_xr);
    cudaGetSymbolAddress((void**)&cmr,  g_cmr);
    cudaGetSymbolAddress((void**)&smr,  g_smr);
    cudaGetSymbolAddress((void**)&wqc,  g_wqc);
    cudaGetSymbolAddress((void**)&wkc,  g_wkc);
    cudaGetSymbolAddress((void**)&wvc,  g_wvc);
    cudaGetSymbolAddress((void**)&wqs,  g_wqs);
    cudaGetSymbolAddress((void**)&wks,  g_wks);
    cudaGetSymbolAddress((void**)&wvs,  g_wvs);
    cudaGetSymbolAddress((void**)&qc,   g_qc);
    cudaGetSymbolAddress((void**)&qf,   g_qf);
    cudaGetSymbolAddress((void**)&kc,   g_kc);
    cudaGetSymbolAddress((void**)&kf,   g_kf);
    cudaGetSymbolAddress((void**)&vcT,  g_vcT);
    cudaGetSymbolAddress((void**)&vfT,  g_vfT);
    cudaGetSymbolAddress((void**)&Sc,   g_Sc);
    cudaGetSymbolAddress((void**)&Ss,   g_Ss);
    cudaGetSymbolAddress((void**)&outc, g_outc);
    cudaGetSymbolAddress((void**)&outs, g_outs);
    cudaGetSymbolAddress((void**)&rsc,  g_rsc);
    cudaGetSymbolAddress((void**)&rss,  g_rss);
    cudaGetSymbolAddress((void**)&qm,   g_qmean);
    cudaGetSymbolAddress((void**)&qv,   g_qvar);
    cudaGetSymbolAddress((void**)&km,   g_kmean);
    cudaGetSymbolAddress((void**)&kv,   g_kvar);

    cudaFuncSetAttribute(gemm_tc<0, 1>, cudaFuncAttributeMaxDynamicSharedMemorySize, GEMM_SMEM);
    cudaFuncSetAttribute(gemm_tc<1, 1>, cudaFuncAttributeMaxDynamicSharedMemorySize, GEMM_SMEM);
    cudaFuncSetAttribute(gemm_tc<2, 1>, cudaFuncAttributeMaxDynamicSharedMemorySize, GEMM_SMEM);
    cudaFuncSetAttribute(gemm_tc<0, 0>, cudaFuncAttributeMaxDynamicSharedMemorySize, GEMM_SMEM);

    // ---- pre-round all external GEMM operands to tf32 (RNA, unbiased) ----
    round_tf32_kern<<<(NB * D + 255) / 256, 256>>>(x,     xr,  NB * D);
    round_tf32_kern<<<(MEM * D + 255) / 256, 256>>>(chmem, cmr, MEM * D);
    round_tf32_kern<<<(MEM * D + 255) / 256, 256>>>(spmem, smr, MEM * D);
    round_tf32_kern<<<(D * D + 255) / 256, 256>>>(chwq, wqc, D * D);
    round_tf32_kern<<<(D * D + 255) / 256, 256>>>(chwk, wkc, D * D);
    round_tf32_kern<<<(D * D + 255) / 256, 256>>>(chwv, wvc, D * D);
    round_tf32_kern<<<(D * D + 255) / 256, 256>>>(spwq, wqs, D * D);
    round_tf32_kern<<<(D * D + 255) / 256, 256>>>(spwk, wks, D * D);
    round_tf32_kern<<<(D * D + 255) / 256, 256>>>(spwv, wvs, D * D);

    const dim3 blk(128);

    // ---- projections (NT form) ----
    gemm_tc<0, 1><<<dim3(D / 128, NB / 128), blk, GEMM_SMEM>>>(xr, wqc, qc, D, D, 0, 0, 0, 0);
    gemm_tc<0, 1><<<dim3(D / 128, NB / 128), blk, GEMM_SMEM>>>(xr, wqs, qf, D, D, 0, 0, 0, 0);
    gemm_tc<0, 1><<<dim3(D / 128, MEM / 128), blk, GEMM_SMEM>>>(cmr, wkc, kc, D, D, 0, 0, 0, 0);
    gemm_tc<0, 1><<<dim3(D / 128, MEM / 128), blk, GEMM_SMEM>>>(smr, wks, kf, D, D, 0, 0, 0, 0);
    // v^T[d,m] = sum_k W[d,k] * mem[m,k]
    gemm_tc<0, 1><<<dim3(MEM / 128, D / 128), blk, GEMM_SMEM>>>(wvc, cmr, vcT, D, MEM, 0, 0, 0, 0);
    gemm_tc<0, 1><<<dim3(MEM / 128, D / 128), blk, GEMM_SMEM>>>(wvs, smr, vfT, D, MEM, 0, 0, 0, 0);

    // ---- SSIM row statistics (on tf32-rounded qf/kf: consistent with GEMM) ----
    row_stats<<<NB,  256>>>(qf, qm, qv);
    row_stats<<<MEM, 256>>>(kf, km, kv);

    // ---- score matrices with fused exp epilogue ----
    gemm_tc<1, 1><<<dim3(MEM / 128, NB / 128), blk, GEMM_SMEM>>>(qc, kc, Sc, D, MEM, 0, 0, 0, 0);
    gemm_tc<2, 1><<<dim3(MEM / 128, NB / 128), blk, GEMM_SMEM>>>(qf, kf, Ss, D, MEM, qm, qv, km, kv);

    // ---- softmax denominators (sums of the same rounded values P@V uses) ----
    row_sum<<<NB, 256>>>(Sc, rsc);
    row_sum<<<NB, 256>>>(Ss, rss);

    // ---- out = P @ V  (V stored transposed -> NT form, K = MEM) ----
    gemm_tc<0, 0><<<dim3(D / 128, NB / 128), blk, GEMM_SMEM>>>(Sc, vcT, outc, MEM, D, 0, 0, 0, 0);
    gemm_tc<0, 0><<<dim3(D / 128, NB / 128), blk, GEMM_SMEM>>>(Ss, vfT, outs, MEM, D, 0, 0, 0, 0);

    // ---- normalize and sum branches ----
    combine<<<NB, 256>>>(outc, outs, rsc, rss, out);
}

// round 8
// speedup vs baseline: 4.4709x; 1.2648x over previous
#include <cuda_runtime.h>
#include <cuda_fp16.h>
#include <cstdint>

#define NB   12544   // 196 * 64
#define D    256
#define MEM  2048

// ---------------- scratch (device globals; no allocation allowed) ----------
__device__ __half g_xh [NB * D];
__device__ __half g_cmh[MEM * D];
__device__ __half g_smh[MEM * D];
__device__ __half g_wqc[D * D];
__device__ __half g_wkc[D * D];
__device__ __half g_wvc[D * D];
__device__ __half g_wqs[D * D];
__device__ __half g_wks[D * D];
__device__ __half g_wvs[D * D];

__device__ __half g_qc [NB * D];
__device__ __half g_qf [NB * D];
__device__ __half g_kc [MEM * D];
__device__ __half g_kf [MEM * D];
__device__ __half g_vcT[D * MEM];
__device__ __half g_vfT[D * MEM];
__device__ __half g_Pc [NB * MEM];
__device__ __half g_Ps [NB * MEM];
__device__ float  g_outc[NB * D];
__device__ float  g_outs[NB * D];
__device__ float  g_rs [2 * NB];
__device__ float  g_qmean[NB];
__device__ float  g_qvar [NB];
__device__ float  g_kmean[MEM];
__device__ float  g_kvar [MEM];

// ---------------------------- helpers --------------------------------------
__device__ __forceinline__ void cpasync16(uint32_t smem, const void* gptr) {
    asm volatile("cp.async.cg.shared.global [%0], [%1], 16;\n"
                 :: "r"(smem), "l"(gptr));
}

__device__ __forceinline__ void mma_f16(float* d, const uint32_t* a,
                                        const uint32_t* b) {
    asm volatile(
        "mma.sync.aligned.m16n8k16.row.col.f32.f16.f16.f32 "
        "{%0,%1,%2,%3},{%4,%5,%6,%7},{%8,%9},{%0,%1,%2,%3};"
        : "+f"(d[0]), "+f"(d[1]), "+f"(d[2]), "+f"(d[3])
        : "r"(a[0]), "r"(a[1]), "r"(a[2]), "r"(a[3]),
          "r"(b[0]), "r"(b[1]));
}

// ---------------------------------------------------------------------------
// fp16 tensor-core NT GEMM: C[M,N] = A[M,K] @ B[N,K]^T   (row-major, ld = K)
// 128x128 block tile, BK=64 halves (128B/row), 4 warps (64x64 each),
// 2-stage cp.async pipeline. blockIdx.z selects operand set {0,1}.
// MODE 0: plain   MODE 1: exp(acc/16)   MODE 2: SSIM -> exp
// OH 1: store C as fp16   OH 0: store C as fp32
// smem row pitch 144B (36 words): fragment LDS bank pattern (4*gid+tig) mod 32
// is a permutation -> conflict-free.
// ---------------------------------------------------------------------------
#define ROWB   144
#define MATB   (128 * ROWB)       // 18432 B per matrix per stage
#define STGB   (2 * MATB)         // 36864 B per stage
#define GEMM_SMEM (2 * STGB)      // 73728 B

template <int M0, int M1, int OH>
__global__ void __launch_bounds__(128, 2)
gemm16(const __half* __restrict__ A0, const __half* __restrict__ B0, void* C0,
       const __half* __restrict__ A1, const __half* __restrict__ B1, void* C1,
       int K, int N,
       const float* __restrict__ qmean, const float* __restrict__ qvar,
       const float* __restrict__ kmean, const float* __restrict__ kvar)
{
    extern __shared__ char smem[];
    const uint32_t sbase = (uint32_t)__cvta_generic_to_shared(smem);

    const __half* A = blockIdx.z ? A1 : A0;
    const __half* B = blockIdx.z ? B1 : B0;
    void*         C = blockIdx.z ? C1 : C0;
    const int   MODE = blockIdx.z ? M1 : M0;

    const int tid  = threadIdx.x;
    const int wid  = tid >> 5;
    const int lane = tid & 31;
    const int m0   = blockIdx.y * 128;
    const int n0   = blockIdx.x * 128;
    const int wm   = (wid & 1) * 64;
    const int wn   = (wid >> 1) * 64;
    const int gid  = lane >> 2;
    const int tig  = lane & 3;

    float acc[4][8][4] = {};
    const int KT = K >> 6;     // BK = 64 halves

    auto load_stage = [&](int kt, int s) {
        const __half* Ag = A + (size_t)(m0 + tid) * K + kt * 64;
        const __half* Bg = B + (size_t)(n0 + tid) * K + kt * 64;
        const uint32_t da = sbase + (uint32_t)(s * STGB + tid * ROWB);
        const uint32_t db = da + MATB;
        #pragma unroll
        for (int c = 0; c < 8; c++) {
            cpasync16(da + c * 16, Ag + c * 8);
            cpasync16(db + c * 16, Bg + c * 8);
        }
        asm volatile("cp.async.commit_group;");
    };

    load_stage(0, 0);

    for (int kt = 0; kt < KT; kt++) {
        if (kt + 1 < KT) {
            load_stage(kt + 1, (kt + 1) & 1);
            asm volatile("cp.async.wait_group 1;");
        } else {
            asm volatile("cp.async.wait_group 0;");
        }
        __syncthreads();

        const uint32_t* aw = (const uint32_t*)(smem + (kt & 1) * STGB);
        const uint32_t* bw = (const uint32_t*)(smem + (kt & 1) * STGB + MATB);

        #pragma unroll
        for (int ks = 0; ks < 4; ks++) {
            const int kw = ks * 8 + tig;       // word offset within 36-word row
            uint32_t af[4][4], bf[8][2];
            #pragma unroll
            for (int mt = 0; mt < 4; mt++) {
                const int r = wm + mt * 16 + gid;
                af[mt][0] = aw[r * 36 + kw];
                af[mt][1] = aw[(r + 8) * 36 + kw];
                af[mt][2] = aw[r * 36 + kw + 4];
                af[mt][3] = aw[(r + 8) * 36 + kw + 4];
            }
            #pragma unroll
            for (int nt = 0; nt < 8; nt++) {
                const int c = wn + nt * 8 + gid;
                bf[nt][0] = bw[c * 36 + kw];
                bf[nt][1] = bw[c * 36 + kw + 4];
            }
            #pragma unroll
            for (int mt = 0; mt < 4; mt++)
                #pragma unroll
                for (int nt = 0; nt < 8; nt++)
                    mma_f16(acc[mt][nt], af[mt], bf[nt]);
        }
        __syncthreads();
    }

    // ------------------------------ epilogue -------------------------------
    float kmv[8][2], kvv[8][2];
    if (MODE == 2) {
        #pragma unroll
        for (int nt = 0; nt < 8; nt++) {
            const int c = n0 + wn + nt * 8 + 2 * tig;
            kmv[nt][0] = kmean[c];   kmv[nt][1] = kmean[c + 1];
            kvv[nt][0] = kvar[c];    kvv[nt][1] = kvar[c + 1];
        }
    }

    #pragma unroll
    for (int mt = 0; mt < 4; mt++) {
        #pragma unroll
        for (int half = 0; half < 2; half++) {
            const int r = m0 + wm + mt * 16 + gid + half * 8;
            float qm_ = 0.f, qv_ = 0.f;
            if (MODE == 2) { qm_ = qmean[r]; qv_ = qvar[r]; }
            #pragma unroll
            for (int nt = 0; nt < 8; nt++) {
                const int c = n0 + wn + nt * 8 + 2 * tig;
                float v0 = acc[mt][nt][half * 2 + 0];
                float v1 = acc[mt][nt][half * 2 + 1];
                if (MODE == 1) {
                    v0 = __expf(v0 * 0.0625f);
                    v1 = __expf(v1 * 0.0625f);
                } else if (MODE == 2) {
                    #pragma unroll
                    for (int j = 0; j < 2; j++) {
                        float& v = j ? v1 : v0;
                        const float km_ = kmv[nt][j];
                        const float kv_ = kvv[nt][j];
                        const float cov = (v - 256.0f * qm_ * km_) * (1.0f / 255.0f);
                        const float num = (2.0f * qm_ * km_ + 0.01f)
                                        * (2.0f * cov + 0.03f);
                        const float den = (qm_ * qm_ + km_ * km_ + 0.01f)
                                        * (qv_ + kv_ + 0.03f);
                        v = __expf(num / (den + 1e-8f));
                    }
                }
                if (OH) {
                    *(__half2*)&((__half*)C)[(size_t)r * N + c] =
                        __floats2half2_rn(v0, v1);
                } else {
                    *(float2*)&((float*)C)[(size_t)r * N + c] =
                        make_float2(v0, v1);
                }
            }
        }
    }
}

// ---------------------------------------------------------------------------
__global__ void f2h(const float* __restrict__ in, __half* __restrict__ out, int n)
{
    const int i = blockIdx.x * 256 + threadIdx.x;
    if (i < n) out[i] = __float2half_rn(in[i]);
}

// ---------------------------------------------------------------------------
// Per-row mean & unbiased variance over 256 columns (fp16 input).
// ---------------------------------------------------------------------------
__global__ void row_stats(const __half* __restrict__ X,
                          float* __restrict__ mean,
                          float* __restrict__ var)
{
    const int row = blockIdx.x;
    const float v = __half2float(X[(size_t)row * 256 + threadIdx.x]);
    float s = v, q = v * v;
    #pragma unroll
    for (int o = 16; o > 0; o >>= 1) {
        s += __shfl_xor_sync(0xFFFFFFFFu, s, o);
        q += __shfl_xor_sync(0xFFFFFFFFu, q, o);
    }
    __shared__ float ssum[8], ssq[8];
    const int w = threadIdx.x >> 5;
    if ((threadIdx.x & 31) == 0) { ssum[w] = s; ssq[w] = q; }
    __syncthreads();
    if (threadIdx.x == 0) {
        float S = 0.f, Q = 0.f;
        #pragma unroll
        for (int i = 0; i < 8; i++) { S += ssum[i]; Q += ssq[i]; }
        const float m = S * (1.0f / 256.0f);
        mean[row] = m;
        var[row]  = (Q - 256.0f * m * m) * (1.0f / 255.0f);
    }
}

// ---------------------------------------------------------------------------
// Row sums of fp16 P matrices [NB, MEM]; blockIdx.y selects branch.
// ---------------------------------------------------------------------------
__global__ void row_sum(const __half* __restrict__ P0,
                        const __half* __restrict__ P1,
                        float* __restrict__ rs)
{
    const __half* P = blockIdx.y ? P1 : P0;
    const int row = blockIdx.x;
    const __half* p = P + (size_t)row * MEM;
    float s = 0.f;
    for (int c = threadIdx.x; c < MEM; c += 256) s += __half2float(p[c]);
    #pragma unroll
    for (int o = 16; o > 0; o >>= 1) s += __shfl_xor_sync(0xFFFFFFFFu, s, o);
    __shared__ float ssum[8];
    const int w = threadIdx.x >> 5;
    if ((threadIdx.x & 31) == 0) ssum[w] = s;
    __syncthreads();
    if (threadIdx.x == 0) {
        float S2 = 0.f;
        #pragma unroll
        for (int i = 0; i < 8; i++) S2 += ssum[i];
        rs[blockIdx.y * NB + row] = S2;
    }
}

// ---------------------------------------------------------------------------
__global__ void combine(const float* __restrict__ outc,
                        const float* __restrict__ outs,
                        const float* __restrict__ rs,
                        float* __restrict__ out)
{
    const int row = blockIdx.x;
    const size_t idx = (size_t)row * 256 + threadIdx.x;
    out[idx] = outc[idx] * (1.0f / rs[row]) + outs[idx] * (1.0f / rs[NB + row]);
}

// ---------------------------------------------------------------------------
extern "C" void kernel_launch(void* const* d_in, const int* in_sizes, int n_in,
                              void* d_out, int out_size)
{
    const float* x     = (const float*)d_in[0];
    const float* chmem = (const float*)d_in[1];
    const float* chwq  = (const float*)d_in[2];
    const float* chwk  = (const float*)d_in[3];
    const float* chwv  = (const float*)d_in[4];
    const float* spmem = (const float*)d_in[5];
    const float* spwq  = (const float*)d_in[6];
    const float* spwk  = (const float*)d_in[7];
    const float* spwv  = (const float*)d_in[8];
    float* out = (float*)d_out;

    __half *xh, *cmh, *smh, *wqc, *wkc, *wvc, *wqs, *wks, *wvs;
    __half *qc, *qf, *kc, *kf, *vcT, *vfT, *Pc, *Ps;
    float *outc, *outs, *rs, *qm, *qv, *km, *kv;
    cudaGetSymbolAddress((void**)&xh,   g_xh);
    cudaGetSymbolAddress((void**)&cmh,  g_cmh);
    cudaGetSymbolAddress((void**)&smh,  g_smh);
    cudaGetSymbolAddress((void**)&wqc,  g_wqc);
    cudaGetSymbolAddress((void**)&wkc,  g_wkc);
    cudaGetSymbolAddress((void**)&wvc,  g_wvc);
    cudaGetSymbolAddress((void**)&wqs,  g_wqs);
    cudaGetSymbolAddress((void**)&wks,  g_wks);
    cudaGetSymbolAddress((void**)&wvs,  g_wvs);
    cudaGetSymbolAddress((void**)&qc,   g_qc);
    cudaGetSymbolAddress((void**)&qf,   g_qf);
    cudaGetSymbolAddress((void**)&kc,   g_kc);
    cudaGetSymbolAddress((void**)&kf,   g_kf);
    cudaGetSymbolAddress((void**)&vcT,  g_vcT);
    cudaGetSymbolAddress((void**)&vfT,  g_vfT);
    cudaGetSymbolAddress((void**)&Pc,   g_Pc);
    cudaGetSymbolAddress((void**)&Ps,   g_Ps);
    cudaGetSymbolAddress((void**)&outc, g_outc);
    cudaGetSymbolAddress((void**)&outs, g_outs);
    cudaGetSymbolAddress((void**)&rs,   g_rs);
    cudaGetSymbolAddress((void**)&qm,   g_qmean);
    cudaGetSymbolAddress((void**)&qv,   g_qvar);
    cudaGetSymbolAddress((void**)&km,   g_kmean);
    cudaGetSymbolAddress((void**)&kv,   g_kvar);

    cudaFuncSetAttribute(gemm16<0, 0, 1>, cudaFuncAttributeMaxDynamicSharedMemorySize, GEMM_SMEM);
    cudaFuncSetAttribute(gemm16<1, 2, 1>, cudaFuncAttributeMaxDynamicSharedMemorySize, GEMM_SMEM);
    cudaFuncSetAttribute(gemm16<0, 0, 0>, cudaFuncAttributeMaxDynamicSharedMemorySize, GEMM_SMEM);

    // ---- convert external operands to fp16 (RNE) ----
    f2h<<<(NB * D + 255) / 256, 256>>>(x,     xh,  NB * D);
    f2h<<<(MEM * D + 255) / 256, 256>>>(chmem, cmh, MEM * D);
    f2h<<<(MEM * D + 255) / 256, 256>>>(spmem, smh, MEM * D);
    f2h<<<(D * D + 255) / 256, 256>>>(chwq, wqc, D * D);
    f2h<<<(D * D + 255) / 256, 256>>>(chwk, wkc, D * D);
    f2h<<<(D * D + 255) / 256, 256>>>(chwv, wvc, D * D);
    f2h<<<(D * D + 255) / 256, 256>>>(spwq, wqs, D * D);
    f2h<<<(D * D + 255) / 256, 256>>>(spwk, wks, D * D);
    f2h<<<(D * D + 255) / 256, 256>>>(spwv, wvs, D * D);

    const dim3 blk(128);

    // ---- projections, branch pairs merged on z ----
    gemm16<0, 0, 1><<<dim3(D / 128, NB / 128, 2), blk, GEMM_SMEM>>>(
        xh, wqc, qc,  xh, wqs, qf,  D, D, 0, 0, 0, 0);
    gemm16<0, 0, 1><<<dim3(D / 128, MEM / 128, 2), blk, GEMM_SMEM>>>(
        cmh, wkc, kc,  smh, wks, kf,  D, D, 0, 0, 0, 0);
    // v^T[d,m] = sum_k W[d,k] * mem[m,k]
    gemm16<0, 0, 1><<<dim3(MEM / 128, D / 128, 2), blk, GEMM_SMEM>>>(
        wvc, cmh, vcT,  wvs, smh, vfT,  D, MEM, 0, 0, 0, 0);

    // ---- SSIM row statistics (on fp16 qf/kf: consistent with GEMM inputs) ----
    row_stats<<<NB,  256>>>(qf, qm, qv);
    row_stats<<<MEM, 256>>>(kf, km, kv);

    // ---- both score matrices in one launch (fused exp epilogues) ----
    gemm16<1, 2, 1><<<dim3(MEM / 128, NB / 128, 2), blk, GEMM_SMEM>>>(
        qc, kc, Pc,  qf, kf, Ps,  D, MEM, qm, qv, km, kv);

    // ---- softmax denominators (sums of the same fp16 values P@V uses) ----
    row_sum<<<dim3(NB, 2), 256>>>(Pc, Ps, rs);

    // ---- both P @ V in one launch (V stored transposed -> NT, K = MEM) ----
    gemm16<0, 0, 0><<<dim3(D / 128, NB / 128, 2), blk, GEMM_SMEM>>>(
        Pc, vcT, outc,  Ps, vfT, outs,  MEM, D, 0, 0, 0, 0);

    // ---- normalize and sum branches ----
    combine<<<NB, 256>>>(outc, outs, rs, out);
}

// round 13
// speedup vs baseline: 4.8745x; 1.0903x over previous
#include <cuda_runtime.h>
#include <cuda_fp16.h>
#include <cstdint>

#define NB   12544   // 196 * 64
#define D    256
#define MEM  2048

// ---------------- scratch (device globals; no allocation allowed) ----------
__device__ __half g_xh [NB * D];
__device__ __half g_cmh[MEM * D];
__device__ __half g_smh[MEM * D];
__device__ __half g_wqc[D * D];
__device__ __half g_wkc[D * D];
__device__ __half g_wvc[D * D];
__device__ __half g_wqs[D * D];
__device__ __half g_wks[D * D];
__device__ __half g_wvs[D * D];

__device__ __half g_qc [NB * D];
__device__ __half g_qf [NB * D];
__device__ __half g_kc [MEM * D];
__device__ __half g_kf [MEM * D];
__device__ __half g_vcT[D * MEM];
__device__ __half g_vfT[D * MEM];
__device__ __half g_Pc [NB * MEM];
__device__ __half g_Ps [NB * MEM];
__device__ float  g_outc0[NB * D];
__device__ float  g_outs0[NB * D];
__device__ float  g_outc1[NB * D];
__device__ float  g_outs1[NB * D];
__device__ float  g_rs [2 * NB];
__device__ float  g_qmean[NB];
__device__ float  g_qvar [NB];
__device__ float  g_kmean[MEM];
__device__ float  g_kvar [MEM];

// ---------------------------- helpers --------------------------------------
__device__ __forceinline__ void cpasync16(uint32_t smem, const void* gptr) {
    asm volatile("cp.async.cg.shared.global [%0], [%1], 16;\n"
                 :: "r"(smem), "l"(gptr));
}

__device__ __forceinline__ void mma_f16(float* d, const uint32_t* a,
                                        const uint32_t* b) {
    asm volatile(
        "mma.sync.aligned.m16n8k16.row.col.f32.f16.f16.f32 "
        "{%0,%1,%2,%3},{%4,%5,%6,%7},{%8,%9},{%0,%1,%2,%3};"
        : "+f"(d[0]), "+f"(d[1]), "+f"(d[2]), "+f"(d[3])
        : "r"(a[0]), "r"(a[1]), "r"(a[2]), "r"(a[3]),
          "r"(b[0]), "r"(b[1]));
}

__device__ __forceinline__ void ldsm4(uint32_t* r, uint32_t addr) {
    asm volatile("ldmatrix.sync.aligned.m8n8.x4.shared.b16 {%0,%1,%2,%3}, [%4];"
                 : "=r"(r[0]), "=r"(r[1]), "=r"(r[2]), "=r"(r[3])
                 : "r"(addr));
}

// ---------------------------------------------------------------------------
// fp16 tensor-core NT GEMM: C[M,N] = A[M,K] @ B[N,K]^T   (row-major, ld = lda)
// 128x128 block tile, BK=64 halves (128B/row), 4 warps (64x64 each),
// 2-stage cp.async pipeline, ldmatrix.x4 fragment loads.
// blockIdx.z: branch = z&1 (operand set), split = z>>1 (K-split, SPLIT=1).
// MODE 0: plain   MODE 1: exp(acc/16)   MODE 2: SSIM -> exp
// OH 1: store C fp16   OH 0: store C fp32
// smem row pitch 144B (36 words) -> ldmatrix phases conflict-free.
// ---------------------------------------------------------------------------
#define ROWB   144
#define MATB   (128 * ROWB)       // 18432 B per matrix per stage
#define STGB   (2 * MATB)         // 36864 B per stage
#define GEMM_SMEM (2 * STGB)      // 73728 B

template <int M0, int M1, int OH, int SPLIT>
__global__ void __launch_bounds__(128, 2)
gemm16(const __half* __restrict__ A0, const __half* __restrict__ B0, void* C0,
       const __half* __restrict__ A1, const __half* __restrict__ B1, void* C1,
       void* C2, void* C3,
       int K, int lda, int N,
       const float* __restrict__ qmean, const float* __restrict__ qvar,
       const float* __restrict__ kmean, const float* __restrict__ kvar)
{
    extern __shared__ char smem[];
    const uint32_t sbase = (uint32_t)__cvta_generic_to_shared(smem);

    const int z      = blockIdx.z;
    const int branch = z & 1;
    const int koff   = SPLIT ? (z >> 1) * K : 0;

    const __half* A = branch ? A1 : A0;
    const __half* B = branch ? B1 : B0;
    void* C;
    if (SPLIT) C = (z == 0) ? C0 : (z == 1) ? C1 : (z == 2) ? C2 : C3;
    else       C = branch ? C1 : C0;
    const int MODE = branch ? M1 : M0;

    const int tid  = threadIdx.x;
    const int wid  = tid >> 5;
    const int lane = tid & 31;
    const int m0   = blockIdx.y * 128;
    const int n0   = blockIdx.x * 128;
    const int wm   = (wid & 1) * 64;
    const int wn   = (wid >> 1) * 64;
    const int gid  = lane >> 2;
    const int tig  = lane & 3;

    // ldmatrix per-lane source addresses (word units within a 36-word row)
    const int rowA  = wm + (lane & 7) + ((lane >> 3) & 1) * 8;
    const int wordA = (lane >> 4) * 4;
    const int rowB  = wn + (lane & 7) + (lane >> 4) * 8;
    const int wordB = ((lane >> 3) & 1) * 4;
    const uint32_t aAb = sbase + (uint32_t)(rowA * ROWB + wordA * 4);
    const uint32_t aBb = sbase + MATB + (uint32_t)(rowB * ROWB + wordB * 4);

    float acc[4][8][4] = {};
    const int KT = K >> 6;     // BK = 64 halves

    auto load_stage = [&](int kt, int s) {
        const __half* Ag = A + (size_t)(m0 + tid) * lda + koff + kt * 64;
        const __half* Bg = B + (size_t)(n0 + tid) * lda + koff + kt * 64;
        const uint32_t da = sbase + (uint32_t)(s * STGB + tid * ROWB);
        const uint32_t db = da + MATB;
        #pragma unroll
        for (int c = 0; c < 8; c++) {
            cpasync16(da + c * 16, Ag + c * 8);
            cpasync16(db + c * 16, Bg + c * 8);
        }
        asm volatile("cp.async.commit_group;");
    };

    load_stage(0, 0);

    for (int kt = 0; kt < KT; kt++) {
        if (kt + 1 < KT) {
            load_stage(kt + 1, (kt + 1) & 1);
            asm volatile("cp.async.wait_group 1;");
        } else {
            asm volatile("cp.async.wait_group 0;");
        }
        __syncthreads();

        const uint32_t stg = (uint32_t)((kt & 1) * STGB);

        #pragma unroll
        for (int ks = 0; ks < 4; ks++) {
            uint32_t af[4][4], bf[4][4];
            #pragma unroll
            for (int mt = 0; mt < 4; mt++)
                ldsm4(af[mt], aAb + stg + (uint32_t)(mt * 16 * ROWB + ks * 32));
            #pragma unroll
            for (int p = 0; p < 4; p++)
                ldsm4(bf[p], aBb + stg + (uint32_t)(p * 16 * ROWB + ks * 32));
            #pragma unroll
            for (int mt = 0; mt < 4; mt++)
                #pragma unroll
                for (int nt = 0; nt < 8; nt++)
                    mma_f16(acc[mt][nt], af[mt], &bf[nt >> 1][(nt & 1) * 2]);
        }
        __syncthreads();
    }

    // ------------------------------ epilogue -------------------------------
    float kmv[8][2], kvv[8][2];
    if (MODE == 2) {
        #pragma unroll
        for (int nt = 0; nt < 8; nt++) {
            const int c = n0 + wn + nt * 8 + 2 * tig;
            kmv[nt][0] = kmean[c];   kmv[nt][1] = kmean[c + 1];
            kvv[nt][0] = kvar[c];    kvv[nt][1] = kvar[c + 1];
        }
    }

    #pragma unroll
    for (int mt = 0; mt < 4; mt++) {
        #pragma unroll
        for (int half = 0; half < 2; half++) {
            const int r = m0 + wm + mt * 16 + gid + half * 8;
            float qm_ = 0.f, qv_ = 0.f;
            if (MODE == 2) { qm_ = qmean[r]; qv_ = qvar[r]; }
            #pragma unroll
            for (int nt = 0; nt < 8; nt++) {
                const int c = n0 + wn + nt * 8 + 2 * tig;
                float v0 = acc[mt][nt][half * 2 + 0];
                float v1 = acc[mt][nt][half * 2 + 1];
                if (MODE == 1) {
                    v0 = __expf(v0 * 0.0625f);
                    v1 = __expf(v1 * 0.0625f);
                } else if (MODE == 2) {
                    #pragma unroll
                    for (int j = 0; j < 2; j++) {
                        float& v = j ? v1 : v0;
                        const float km_ = kmv[nt][j];
                        const float kv_ = kvv[nt][j];
                        const float cov = (v - 256.0f * qm_ * km_) * (1.0f / 255.0f);
                        const float num = (2.0f * qm_ * km_ + 0.01f)
                                        * (2.0f * cov + 0.03f);
                        const float den = (qm_ * qm_ + km_ * km_ + 0.01f)
                                        * (qv_ + kv_ + 0.03f);
                        v = __expf(num / (den + 1e-8f));
                    }
                }
                if (OH) {
                    *(__half2*)&((__half*)C)[(size_t)r * N + c] =
                        __floats2half2_rn(v0, v1);
                } else {
                    *(float2*)&((float*)C)[(size_t)r * N + c] =
                        make_float2(v0, v1);
                }
            }
        }
    }
}

// ---------------------------------------------------------------------------
// One launch converting all 9 fp32 operands to fp16 (grid.y = segment).
// All segment sizes are multiples of 4; float4 -> 2x half2.
// ---------------------------------------------------------------------------
__global__ void f2h_all(const float* s0, __half* d0, const float* s1, __half* d1,
                        const float* s2, __half* d2, const float* s3, __half* d3,
                        const float* s4, __half* d4, const float* s5, __half* d5,
                        const float* s6, __half* d6, const float* s7, __half* d7,
                        const float* s8, __half* d8)
{
    const float* s; __half* d; int n;
    switch (blockIdx.y) {
        case 0: s = s0; d = d0; n = NB * D;  break;
        case 1: s = s1; d = d1; n = MEM * D; break;
        case 2: s = s2; d = d2; n = MEM * D; break;
        case 3: s = s3; d = d3; n = D * D;   break;
        case 4: s = s4; d = d4; n = D * D;   break;
        case 5: s = s5; d = d5; n = D * D;   break;
        case 6: s = s6; d = d6; n = D * D;   break;
        case 7: s = s7; d = d7; n = D * D;   break;
        default: s = s8; d = d8; n = D * D;  break;
    }
    const int n4 = n >> 2;
    for (int i = blockIdx.x * 256 + threadIdx.x; i < n4; i += gridDim.x * 256) {
        const float4 v = ((const float4*)s)[i];
        ((__half2*)d)[2 * i]     = __floats2half2_rn(v.x, v.y);
        ((__half2*)d)[2 * i + 1] = __floats2half2_rn(v.z, v.w);
    }
}

// ---------------------------------------------------------------------------
__global__ void row_stats(const __half* __restrict__ X,
                          float* __restrict__ mean,
                          float* __restrict__ var)
{
    const int row = blockIdx.x;
    const float v = __half2float(X[(size_t)row * 256 + threadIdx.x]);
    float s = v, q = v * v;
    #pragma unroll
    for (int o = 16; o > 0; o >>= 1) {
        s += __shfl_xor_sync(0xFFFFFFFFu, s, o);
        q += __shfl_xor_sync(0xFFFFFFFFu, q, o);
    }
    __shared__ float ssum[8], ssq[8];
    const int w = threadIdx.x >> 5;
    if ((threadIdx.x & 31) == 0) { ssum[w] = s; ssq[w] = q; }
    __syncthreads();
    if (threadIdx.x == 0) {
        float S = 0.f, Q = 0.f;
        #pragma unroll
        for (int i = 0; i < 8; i++) { S += ssum[i]; Q += ssq[i]; }
        const float m = S * (1.0f / 256.0f);
        mean[row] = m;
        var[row]  = (Q - 256.0f * m * m) * (1.0f / 255.0f);
    }
}

// ---------------------------------------------------------------------------
__global__ void row_sum(const __half* __restrict__ P0,
                        const __half* __restrict__ P1,
                        float* __restrict__ rs)
{
    const __half* P = blockIdx.y ? P1 : P0;
    const int row = blockIdx.x;
    const __half2* p = (const __half2*)(P + (size_t)row * MEM);
    float s = 0.f;
    for (int c = threadIdx.x; c < MEM / 2; c += 256) {
        const float2 v = __half22float2(p[c]);
        s += v.x + v.y;
    }
    #pragma unroll
    for (int o = 16; o > 0; o >>= 1) s += __shfl_xor_sync(0xFFFFFFFFu, s, o);
    __shared__ float ssum[8];
    const int w = threadIdx.x >> 5;
    if ((threadIdx.x & 31) == 0) ssum[w] = s;
    __syncthreads();
    if (threadIdx.x == 0) {
        float S2 = 0.f;
        #pragma unroll
        for (int i = 0; i < 8; i++) S2 += ssum[i];
        rs[blockIdx.y * NB + row] = S2;
    }
}

// ---------------------------------------------------------------------------
__global__ void combine(const float* __restrict__ outc0,
                        const float* __restrict__ outc1,
                        const float* __restrict__ outs0,
                        const float* __restrict__ outs1,
                        const float* __restrict__ rs,
                        float* __restrict__ out)
{
    const int row = blockIdx.x;
    const size_t idx = (size_t)row * 256 + threadIdx.x;
    out[idx] = (outc0[idx] + outc1[idx]) * (1.0f / rs[row])
             + (outs0[idx] + outs1[idx]) * (1.0f / rs[NB + row]);
}

// ---------------------------------------------------------------------------
extern "C" void kernel_launch(void* const* d_in, const int* in_sizes, int n_in,
                              void* d_out, int out_size)
{
    const float* x     = (const float*)d_in[0];
    const float* chmem = (const float*)d_in[1];
    const float* chwq  = (const float*)d_in[2];
    const float* chwk  = (const float*)d_in[3];
    const float* chwv  = (const float*)d_in[4];
    const float* spmem = (const float*)d_in[5];
    const float* spwq  = (const float*)d_in[6];
    const float* spwk  = (const float*)d_in[7];
    const float* spwv  = (const float*)d_in[8];
    float* out = (float*)d_out;

    __half *xh, *cmh, *smh, *wqc, *wkc, *wvc, *wqs, *wks, *wvs;
    __half *qc, *qf, *kc, *kf, *vcT, *vfT, *Pc, *Ps;
    float *outc0, *outs0, *outc1, *outs1, *rs, *qm, *qv, *km, *kv;
    cudaGetSymbolAddress((void**)&xh,   g_xh);
    cudaGetSymbolAddress((void**)&cmh,  g_cmh);
    cudaGetSymbolAddress((void**)&smh,  g_smh);
    cudaGetSymbolAddress((void**)&wqc,  g_wqc);
    cudaGetSymbolAddress((void**)&wkc,  g_wkc);
    cudaGetSymbolAddress((void**)&wvc,  g_wvc);
    cudaGetSymbolAddress((void**)&wqs,  g_wqs);
    cudaGetSymbolAddress((void**)&wks,  g_wks);
    cudaGetSymbolAddress((void**)&wvs,  g_wvs);
    cudaGetSymbolAddress((void**)&qc,   g_qc);
    cudaGetSymbolAddress((void**)&qf,   g_qf);
    cudaGetSymbolAddress((void**)&kc,   g_kc);
    cudaGetSymbolAddress((void**)&kf,   g_kf);
    cudaGetSymbolAddress((void**)&vcT,  g_vcT);
    cudaGetSymbolAddress((void**)&vfT,  g_vfT);
    cudaGetSymbolAddress((void**)&Pc,   g_Pc);
    cudaGetSymbolAddress((void**)&Ps,   g_Ps);
    cudaGetSymbolAddress((void**)&outc0, g_outc0);
    cudaGetSymbolAddress((void**)&outs0, g_outs0);
    cudaGetSymbolAddress((void**)&outc1, g_outc1);
    cudaGetSymbolAddress((void**)&outs1, g_outs1);
    cudaGetSymbolAddress((void**)&rs,   g_rs);
    cudaGetSymbolAddress((void**)&qm,   g_qmean);
    cudaGetSymbolAddress((void**)&qv,   g_qvar);
    cudaGetSymbolAddress((void**)&km,   g_kmean);
    cudaGetSymbolAddress((void**)&kv,   g_kvar);

    cudaFuncSetAttribute(gemm16<0, 0, 1, 0>, cudaFuncAttributeMaxDynamicSharedMemorySize, GEMM_SMEM);
    cudaFuncSetAttribute(gemm16<1, 2, 1, 0>, cudaFuncAttributeMaxDynamicSharedMemorySize, GEMM_SMEM);
    cudaFuncSetAttribute(gemm16<0, 0, 0, 1>, cudaFuncAttributeMaxDynamicSharedMemorySize, GEMM_SMEM);

    // ---- convert all external operands to fp16 (single launch) ----
    f2h_all<<<dim3(64, 9), 256>>>(x, xh, chmem, cmh, spmem, smh,
                                  chwq, wqc, chwk, wkc, chwv, wvc,
                                  spwq, wqs, spwk, wks, spwv, wvs);

    const dim3 blk(128);

    // ---- projections, branch pairs merged on z ----
    gemm16<0, 0, 1, 0><<<dim3(D / 128, NB / 128, 2), blk, GEMM_SMEM>>>(
        xh, wqc, qc,  xh, wqs, qf,  0, 0,  D, D, D, 0, 0, 0, 0);
    gemm16<0, 0, 1, 0><<<dim3(D / 128, MEM / 128, 2), blk, GEMM_SMEM>>>(
        cmh, wkc, kc,  smh, wks, kf,  0, 0,  D, D, D, 0, 0, 0, 0);
    // v^T[d,m] = sum_k W[d,k] * mem[m,k]
    gemm16<0, 0, 1, 0><<<dim3(MEM / 128, D / 128, 2), blk, GEMM_SMEM>>>(
        wvc, cmh, vcT,  wvs, smh, vfT,  0, 0,  D, D, MEM, 0, 0, 0, 0);

    // ---- SSIM row statistics (on fp16 qf/kf: consistent with GEMM inputs) ----
    row_stats<<<NB,  256>>>(qf, qm, qv);
    row_stats<<<MEM, 256>>>(kf, km, kv);

    // ---- both score matrices in one launch (fused exp epilogues) ----
    gemm16<1, 2, 1, 0><<<dim3(MEM / 128, NB / 128, 2), blk, GEMM_SMEM>>>(
        qc, kc, Pc,  qf, kf, Ps,  0, 0,  D, D, MEM, qm, qv, km, kv);

    // ---- softmax denominators ----
    row_sum<<<dim3(NB, 2), 256>>>(Pc, Ps, rs);

    // ---- P @ V, both branches + K-split 2 in one launch (z = 4) ----
    gemm16<0, 0, 0, 1><<<dim3(D / 128, NB / 128, 4), blk, GEMM_SMEM>>>(
        Pc, vcT, outc0,  Ps, vfT, outs0,  outc1, outs1,
        MEM / 2, MEM, D, 0, 0, 0, 0);

    // ---- normalize and sum branches ----
    combine<<<NB, 256>>>(outc0, outc1, outs0, outs1, rs, out);
}

// round 15
// speedup vs baseline: 5.1709x; 1.0608x over previous
#include <cuda_runtime.h>
#include <cuda_fp16.h>
#include <cstdint>

#define NB   12544   // 196 * 64
#define D    256
#define MEM  2048

// ---------------- scratch (device globals; no allocation allowed) ----------
__device__ __half g_xh [NB * D];
__device__ __half g_cmh[MEM * D];
__device__ __half g_smh[MEM * D];
__device__ __half g_wqc[D * D];
__device__ __half g_wkc[D * D];
__device__ __half g_wvc[D * D];
__device__ __half g_wqs[D * D];
__device__ __half g_wks[D * D];
__device__ __half g_wvs[D * D];

__device__ __half g_qc [NB * D];
__device__ __half g_qf [NB * D];
__device__ __half g_kc [MEM * D];
__device__ __half g_kf [MEM * D];
__device__ __half g_vcT[D * MEM];
__device__ __half g_vfT[D * MEM];
__device__ __half g_Pc [NB * MEM];
__device__ __half g_Ps [NB * MEM];
__device__ float  g_outc0[NB * D];
__device__ float  g_outs0[NB * D];
__device__ float  g_outc1[NB * D];
__device__ float  g_outs1[NB * D];
__device__ float  g_rs [2 * NB];
__device__ float  g_qmean[NB];
__device__ float  g_qvar [NB];
__device__ float  g_kmean[MEM];
__device__ float  g_kvar [MEM];

// ---------------------------- helpers --------------------------------------
__device__ __forceinline__ void cpasync16(uint32_t smem, const void* gptr) {
    asm volatile("cp.async.cg.shared.global [%0], [%1], 16;\n"
                 :: "r"(smem), "l"(gptr));
}

__device__ __forceinline__ void mma_f16(float* d, const uint32_t* a,
                                        const uint32_t* b) {
    asm volatile(
        "mma.sync.aligned.m16n8k16.row.col.f32.f16.f16.f32 "
        "{%0,%1,%2,%3},{%4,%5,%6,%7},{%8,%9},{%0,%1,%2,%3};"
        : "+f"(d[0]), "+f"(d[1]), "+f"(d[2]), "+f"(d[3])
        : "r"(a[0]), "r"(a[1]), "r"(a[2]), "r"(a[3]),
          "r"(b[0]), "r"(b[1]));
}

__device__ __forceinline__ void ldsm4(uint32_t* r, uint32_t addr) {
    asm volatile("ldmatrix.sync.aligned.m8n8.x4.shared.b16 {%0,%1,%2,%3}, [%4];"
                 : "=r"(r[0]), "=r"(r[1]), "=r"(r[2]), "=r"(r[3])
                 : "r"(addr));
}

// ---------------------------------------------------------------------------
// fp16 tensor-core NT GEMM: C[M,N] = A[M,K] @ B[N,K]^T   (row-major, ld = lda)
// 128x128 block tile, BK=64 halves (128B/row), 4 warps (64x64 each),
// 3-stage cp.async pipeline, ONE __syncthreads per BK iter, ldmatrix.x4.
// blockIdx.z: branch = z&1 (operand set), split = z>>1 (K-split, SPLIT=1).
// MODE 0: plain   MODE 1: exp(acc/16)   MODE 2: SSIM -> exp
// OH 1: store C fp16   OH 0: store C fp32
// M0!=0 (score kernels): fused row-sum of rounded P via atomicAdd into rsum.
// smem row pitch 144B (36 words) -> ldmatrix phases conflict-free.
// ---------------------------------------------------------------------------
#define ROWB   144
#define MATB   (128 * ROWB)       // 18432 B per matrix per stage
#define STGB   (2 * MATB)         // 36864 B per stage
#define GEMM_SMEM (3 * STGB)      // 110592 B (3 stages)

template <int M0, int M1, int OH, int SPLIT>
__global__ void __launch_bounds__(128, 2)
gemm16(const __half* __restrict__ A0, const __half* __restrict__ B0, void* C0,
       const __half* __restrict__ A1, const __half* __restrict__ B1, void* C1,
       void* C2, void* C3,
       int K, int lda, int N,
       const float* __restrict__ qmean, const float* __restrict__ qvar,
       const float* __restrict__ kmean, const float* __restrict__ kvar,
       float* __restrict__ rsum)
{
    extern __shared__ char smem[];
    const uint32_t sbase = (uint32_t)__cvta_generic_to_shared(smem);

    const int z      = blockIdx.z;
    const int branch = z & 1;
    const int koff   = SPLIT ? (z >> 1) * K : 0;

    const __half* A = branch ? A1 : A0;
    const __half* B = branch ? B1 : B0;
    void* C;
    if (SPLIT) C = (z == 0) ? C0 : (z == 1) ? C1 : (z == 2) ? C2 : C3;
    else       C = branch ? C1 : C0;
    const int MODE = branch ? M1 : M0;

    const int tid  = threadIdx.x;
    const int wid  = tid >> 5;
    const int lane = tid & 31;
    const int m0   = blockIdx.y * 128;
    const int n0   = blockIdx.x * 128;
    const int wm   = (wid & 1) * 64;
    const int wn   = (wid >> 1) * 64;
    const int gid  = lane >> 2;
    const int tig  = lane & 3;

    // ldmatrix per-lane source addresses (word units within a 36-word row)
    const int rowA  = wm + (lane & 7) + ((lane >> 3) & 1) * 8;
    const int wordA = (lane >> 4) * 4;
    const int rowB  = wn + (lane & 7) + (lane >> 4) * 8;
    const int wordB = ((lane >> 3) & 1) * 4;
    const uint32_t aAb = sbase + (uint32_t)(rowA * ROWB + wordA * 4);
    const uint32_t aBb = sbase + MATB + (uint32_t)(rowB * ROWB + wordB * 4);

    float acc[4][8][4] = {};
    const int KT = K >> 6;     // BK = 64 halves

    auto load_stage = [&](int kt, int s) {
        const __half* Ag = A + (size_t)(m0 + tid) * lda + koff + kt * 64;
        const __half* Bg = B + (size_t)(n0 + tid) * lda + koff + kt * 64;
        const uint32_t da = sbase + (uint32_t)(s * STGB + tid * ROWB);
        const uint32_t db = da + MATB;
        #pragma unroll
        for (int c = 0; c < 8; c++) {
            cpasync16(da + c * 16, Ag + c * 8);
            cpasync16(db + c * 16, Bg + c * 8);
        }
        asm volatile("cp.async.commit_group;");
    };

    load_stage(0, 0);
    if (KT > 1) load_stage(1, 1);

    for (int kt = 0; kt < KT; kt++) {
        // protects the stage the upcoming load overwrites (read at iter kt-1)
        __syncthreads();

        if (kt + 2 < KT) load_stage(kt + 2, (kt + 2) % 3);

        // outstanding groups newer than chunk kt
        const int n_out = ((kt + 2 < KT) ? (kt + 2) : (KT - 1)) - kt;
        if (n_out == 2)      asm volatile("cp.async.wait_group 2;");
        else if (n_out == 1) asm volatile("cp.async.wait_group 1;");
        else                 asm volatile("cp.async.wait_group 0;");
        __syncwarp();

        const uint32_t stg = (uint32_t)((kt % 3) * STGB);

        #pragma unroll
        for (int ks = 0; ks < 4; ks++) {
            uint32_t af[4][4], bf[4][4];
            #pragma unroll
            for (int mt = 0; mt < 4; mt++)
                ldsm4(af[mt], aAb + stg + (uint32_t)(mt * 16 * ROWB + ks * 32));
            #pragma unroll
            for (int p = 0; p < 4; p++)
                ldsm4(bf[p], aBb + stg + (uint32_t)(p * 16 * ROWB + ks * 32));
            #pragma unroll
            for (int mt = 0; mt < 4; mt++)
                #pragma unroll
                for (int nt = 0; nt < 8; nt++)
                    mma_f16(acc[mt][nt], af[mt], &bf[nt >> 1][(nt & 1) * 2]);
        }
    }

    // ------------------------------ epilogue -------------------------------
    float kmv[8][2], kvv[8][2];
    if (MODE == 2) {
        #pragma unroll
        for (int nt = 0; nt < 8; nt++) {
            const int c = n0 + wn + nt * 8 + 2 * tig;
            kmv[nt][0] = kmean[c];   kmv[nt][1] = kmean[c + 1];
            kvv[nt][0] = kvar[c];    kvv[nt][1] = kvar[c + 1];
        }
    }

    #pragma unroll
    for (int mt = 0; mt < 4; mt++) {
        #pragma unroll
        for (int half = 0; half < 2; half++) {
            const int r = m0 + wm + mt * 16 + gid + half * 8;
            float qm_ = 0.f, qv_ = 0.f;
            if (MODE == 2) { qm_ = qmean[r]; qv_ = qvar[r]; }
            float rsm = 0.f;
            #pragma unroll
            for (int nt = 0; nt < 8; nt++) {
                const int c = n0 + wn + nt * 8 + 2 * tig;
                float v0 = acc[mt][nt][half * 2 + 0];
                float v1 = acc[mt][nt][half * 2 + 1];
                if (MODE == 1) {
                    v0 = __expf(v0 * 0.0625f);
                    v1 = __expf(v1 * 0.0625f);
                } else if (MODE == 2) {
                    #pragma unroll
                    for (int j = 0; j < 2; j++) {
                        float& v = j ? v1 : v0;
                        const float km_ = kmv[nt][j];
                        const float kv_ = kvv[nt][j];
                        const float cov = (v - 256.0f * qm_ * km_) * (1.0f / 255.0f);
                        const float num = (2.0f * qm_ * km_ + 0.01f)
                                        * (2.0f * cov + 0.03f);
                        const float den = (qm_ * qm_ + km_ * km_ + 0.01f)
                                        * (qv_ + kv_ + 0.03f);
                        v = __expf(num / (den + 1e-8f));
                    }
                }
                if (OH) {
                    const __half2 h = __floats2half2_rn(v0, v1);
                    *(__half2*)&((__half*)C)[(size_t)r * N + c] = h;
                    if (M0 != 0) {                 // fused row-sum (score)
                        const float2 f = __half22float2(h);
                        rsm += f.x + f.y;
                    }
                } else {
                    *(float2*)&((float*)C)[(size_t)r * N + c] =
                        make_float2(v0, v1);
                }
            }
            if (OH && M0 != 0) {
                // reduce over the 4 tig lanes that share this row
                rsm += __shfl_xor_sync(0xFFFFFFFFu, rsm, 1);
                rsm += __shfl_xor_sync(0xFFFFFFFFu, rsm, 2);
                if (tig == 0)
                    atomicAdd(&rsum[branch * NB + r], rsm);
            }
        }
    }
}

// ---------------------------------------------------------------------------
// One launch converting all 9 fp32 operands to fp16 (grid.y = segment).
// ---------------------------------------------------------------------------
__global__ void f2h_all(const float* s0, __half* d0, const float* s1, __half* d1,
                        const float* s2, __half* d2, const float* s3, __half* d3,
                        const float* s4, __half* d4, const float* s5, __half* d5,
                        const float* s6, __half* d6, const float* s7, __half* d7,
                        const float* s8, __half* d8)
{
    const float* s; __half* d; int n;
    switch (blockIdx.y) {
        case 0: s = s0; d = d0; n = NB * D;  break;
        case 1: s = s1; d = d1; n = MEM * D; break;
        case 2: s = s2; d = d2; n = MEM * D; break;
        case 3: s = s3; d = d3; n = D * D;   break;
        case 4: s = s4; d = d4; n = D * D;   break;
        case 5: s = s5; d = d5; n = D * D;   break;
        case 6: s = s6; d = d6; n = D * D;   break;
        case 7: s = s7; d = d7; n = D * D;   break;
        default: s = s8; d = d8; n = D * D;  break;
    }
    const int n4 = n >> 2;
    for (int i = blockIdx.x * 256 + threadIdx.x; i < n4; i += gridDim.x * 256) {
        const float4 v = ((const float4*)s)[i];
        ((__half2*)d)[2 * i]     = __floats2half2_rn(v.x, v.y);
        ((__half2*)d)[2 * i + 1] = __floats2half2_rn(v.z, v.w);
    }
}

// ---------------------------------------------------------------------------
// Per-row mean & unbiased variance over 256 cols for qf (rows<NB) and kf.
// ---------------------------------------------------------------------------
__global__ void row_stats2(const __half* __restrict__ qf,
                           const __half* __restrict__ kf,
                           float* __restrict__ qmean, float* __restrict__ qvar,
                           float* __restrict__ kmean, float* __restrict__ kvar)
{
    const int row = blockIdx.x;
    const __half* X; float *mean, *var; int r;
    if (row < NB) { X = qf; mean = qmean; var = qvar; r = row; }
    else          { X = kf; mean = kmean; var = kvar; r = row - NB; }

    const float v = __half2float(X[(size_t)r * 256 + threadIdx.x]);
    float s = v, q = v * v;
    #pragma unroll
    for (int o = 16; o > 0; o >>= 1) {
        s += __shfl_xor_sync(0xFFFFFFFFu, s, o);
        q += __shfl_xor_sync(0xFFFFFFFFu, q, o);
    }
    __shared__ float ssum[8], ssq[8];
    const int w = threadIdx.x >> 5;
    if ((threadIdx.x & 31) == 0) { ssum[w] = s; ssq[w] = q; }
    __syncthreads();
    if (threadIdx.x == 0) {
        float S = 0.f, Q = 0.f;
        #pragma unroll
        for (int i = 0; i < 8; i++) { S += ssum[i]; Q += ssq[i]; }
        const float m = S * (1.0f / 256.0f);
        mean[r] = m;
        var[r]  = (Q - 256.0f * m * m) * (1.0f / 255.0f);
    }
}

// ---------------------------------------------------------------------------
__global__ void combine(const float* __restrict__ outc0,
                        const float* __restrict__ outc1,
                        const float* __restrict__ outs0,
                        const float* __restrict__ outs1,
                        const float* __restrict__ rs,
                        float* __restrict__ out)
{
    const int row = blockIdx.x;
    const size_t idx = (size_t)row * 256 + threadIdx.x;
    out[idx] = (outc0[idx] + outc1[idx]) * (1.0f / rs[row])
             + (outs0[idx] + outs1[idx]) * (1.0f / rs[NB + row]);
}

// ---------------------------------------------------------------------------
extern "C" void kernel_launch(void* const* d_in, const int* in_sizes, int n_in,
                              void* d_out, int out_size)
{
    const float* x     = (const float*)d_in[0];
    const float* chmem = (const float*)d_in[1];
    const float* chwq  = (const float*)d_in[2];
    const float* chwk  = (const float*)d_in[3];
    const float* chwv  = (const float*)d_in[4];
    const float* spmem = (const float*)d_in[5];
    const float* spwq  = (const float*)d_in[6];
    const float* spwk  = (const float*)d_in[7];
    const float* spwv  = (const float*)d_in[8];
    float* out = (float*)d_out;

    __half *xh, *cmh, *smh, *wqc, *wkc, *wvc, *wqs, *wks, *wvs;
    __half *qc, *qf, *kc, *kf, *vcT, *vfT, *Pc, *Ps;
    float *outc0, *outs0, *outc1, *outs1, *rs, *qm, *qv, *km, *kv;
    cudaGetSymbolAddress((void**)&xh,   g_xh);
    cudaGetSymbolAddress((void**)&cmh,  g_cmh);
    cudaGetSymbolAddress((void**)&smh,  g_smh);
    cudaGetSymbolAddress((void**)&wqc,  g_wqc);
    cudaGetSymbolAddress((void**)&wkc,  g_wkc);
    cudaGetSymbolAddress((void**)&wvc,  g_wvc);
    cudaGetSymbolAddress((void**)&wqs,  g_wqs);
    cudaGetSymbolAddress((void**)&wks,  g_wks);
    cudaGetSymbolAddress((void**)&wvs,  g_wvs);
    cudaGetSymbolAddress((void**)&qc,   g_qc);
    cudaGetSymbolAddress((void**)&qf,   g_qf);
    cudaGetSymbolAddress((void**)&kc,   g_kc);
    cudaGetSymbolAddress((void**)&kf,   g_kf);
    cudaGetSymbolAddress((void**)&vcT,  g_vcT);
    cudaGetSymbolAddress((void**)&vfT,  g_vfT);
    cudaGetSymbolAddress((void**)&Pc,   g_Pc);
    cudaGetSymbolAddress((void**)&Ps,   g_Ps);
    cudaGetSymbolAddress((void**)&outc0, g_outc0);
    cudaGetSymbolAddress((void**)&outs0, g_outs0);
    cudaGetSymbolAddress((void**)&outc1, g_outc1);
    cudaGetSymbolAddress((void**)&outs1, g_outs1);
    cudaGetSymbolAddress((void**)&rs,   g_rs);
    cudaGetSymbolAddress((void**)&qm,   g_qmean);
    cudaGetSymbolAddress((void**)&qv,   g_qvar);
    cudaGetSymbolAddress((void**)&km,   g_kmean);
    cudaGetSymbolAddress((void**)&kv,   g_kvar);

    cudaFuncSetAttribute(gemm16<0, 0, 1, 0>, cudaFuncAttributeMaxDynamicSharedMemorySize, GEMM_SMEM);
    cudaFuncSetAttribute(gemm16<1, 2, 1, 0>, cudaFuncAttributeMaxDynamicSharedMemorySize, GEMM_SMEM);
    cudaFuncSetAttribute(gemm16<0, 0, 0, 1>, cudaFuncAttributeMaxDynamicSharedMemorySize, GEMM_SMEM);

    // ---- convert all external operands to fp16 (single launch) ----
    f2h_all<<<dim3(64, 9), 256>>>(x, xh, chmem, cmh, spmem, smh,
                                  chwq, wqc, chwk, wkc, chwv, wvc,
                                  spwq, wqs, spwk, wks, spwv, wvs);

    // ---- zero the fused row-sum accumulators (graph-capturable memset) ----
    cudaMemsetAsync(rs, 0, 2 * NB * sizeof(float));

    const dim3 blk(128);

    // ---- projections, branch pairs merged on z ----
    gemm16<0, 0, 1, 0><<<dim3(D / 128, NB / 128, 2), blk, GEMM_SMEM>>>(
        xh, wqc, qc,  xh, wqs, qf,  0, 0,  D, D, D, 0, 0, 0, 0, rs);
    gemm16<0, 0, 1, 0><<<dim3(D / 128, MEM / 128, 2), blk, GEMM_SMEM>>>(
        cmh, wkc, kc,  smh, wks, kf,  0, 0,  D, D, D, 0, 0, 0, 0, rs);
    // v^T[d,m] = sum_k W[d,k] * mem[m,k]
    gemm16<0, 0, 1, 0><<<dim3(MEM / 128, D / 128, 2), blk, GEMM_SMEM>>>(
        wvc, cmh, vcT,  wvs, smh, vfT,  0, 0,  D, D, MEM, 0, 0, 0, 0, rs);

    // ---- SSIM row statistics (qf rows then kf rows, one launch) ----
    row_stats2<<<NB + MEM, 256>>>(qf, kf, qm, qv, km, kv);

    // ---- both score matrices, fused exp epilogue + fused row-sums ----
    gemm16<1, 2, 1, 0><<<dim3(MEM / 128, NB / 128, 2), blk, GEMM_SMEM>>>(
        qc, kc, Pc,  qf, kf, Ps,  0, 0,  D, D, MEM, qm, qv, km, kv, rs);

    // ---- P @ V, both branches + K-split 2 in one launch (z = 4) ----
    gemm16<0, 0, 0, 1><<<dim3(D / 128, NB / 128, 4), blk, GEMM_SMEM>>>(
        Pc, vcT, outc0,  Ps, vfT, outs0,  outc1, outs1,
        MEM / 2, MEM, D, 0, 0, 0, 0, rs);

    // ---- normalize and sum branches ----
    combine<<<NB, 256>>>(outc0, outc1, outs0, outs1, rs, out);
}

// round 16
// speedup vs baseline: 5.6353x; 1.0898x over previous
#include <cuda_runtime.h>
#include <cuda_fp16.h>
#include <cstdint>

#define NB   12544   // 196 * 64
#define D    256
#define MEM  2048

// ---------------- scratch (device globals; no allocation allowed) ----------
__device__ __half g_xh [NB * D];
__device__ __half g_cmh[MEM * D];
__device__ __half g_smh[MEM * D];
__device__ __half g_wqc[D * D];
__device__ __half g_wkc[D * D];
__device__ __half g_wvc[D * D];
__device__ __half g_wqs[D * D];
__device__ __half g_wks[D * D];
__device__ __half g_wvs[D * D];

__device__ __half g_qc [NB * D];
__device__ __half g_qf [NB * D];
__device__ __half g_kc [MEM * D];
__device__ __half g_kf [MEM * D];
__device__ __half g_vcT[D * MEM];
__device__ __half g_vfT[D * MEM];
__device__ __half g_Pc [NB * MEM];
__device__ __half g_Ps [NB * MEM];
__device__ float  g_outc0[NB * D];
__device__ float  g_outs0[NB * D];
__device__ float  g_outc1[NB * D];
__device__ float  g_outs1[NB * D];
__device__ float  g_rs [2 * NB];
__device__ float  g_qmean[NB];
__device__ float  g_qvar [NB];
__device__ float  g_kmean[MEM];
__device__ float  g_kvar [MEM];

// ---------------------------- helpers --------------------------------------
__device__ __forceinline__ void cpasync16(uint32_t smem, const void* gptr) {
    asm volatile("cp.async.cg.shared.global [%0], [%1], 16;\n"
                 :: "r"(smem), "l"(gptr));
}

__device__ __forceinline__ void mma_f16(float* d, const uint32_t* a,
                                        const uint32_t* b) {
    asm volatile(
        "mma.sync.aligned.m16n8k16.row.col.f32.f16.f16.f32 "
        "{%0,%1,%2,%3},{%4,%5,%6,%7},{%8,%9},{%0,%1,%2,%3};"
        : "+f"(d[0]), "+f"(d[1]), "+f"(d[2]), "+f"(d[3])
        : "r"(a[0]), "r"(a[1]), "r"(a[2]), "r"(a[3]),
          "r"(b[0]), "r"(b[1]));
}

__device__ __forceinline__ void ldsm4(uint32_t* r, uint32_t addr) {
    asm volatile("ldmatrix.sync.aligned.m8n8.x4.shared.b16 {%0,%1,%2,%3}, [%4];"
                 : "=r"(r[0]), "=r"(r[1]), "=r"(r[2]), "=r"(r[3])
                 : "r"(addr));
}

// ---------------------------------------------------------------------------
// fp16 tensor-core NT GEMM: C[M,N] = A[M,K] @ B[N,K]^T   (row-major, ld = lda)
// 128x128 block tile, BK=64 halves (128B/row), 256 threads = 8 warps of
// 64x32 each, 3-stage cp.async pipeline, ONE __syncthreads per BK iter,
// ldmatrix.x4 fragment loads. 2 CTAs/SM -> 16 warps/SM for latency hiding.
// blockIdx.z: branch = z&1 (operand set), split = z>>1 (K-split, SPLIT=1).
// MODE 0: plain   MODE 1: exp(acc/16)   MODE 2: SSIM -> exp
// OH 1: store C fp16   OH 0: store C fp32
// M0!=0 (score kernels): fused row-sum of rounded P via atomicAdd into rsum.
// smem row pitch 144B (36 words) -> ldmatrix phases conflict-free.
// ---------------------------------------------------------------------------
#define ROWB   144
#define MATB   (128 * ROWB)       // 18432 B per matrix per stage
#define STGB   (2 * MATB)         // 36864 B per stage
#define GEMM_SMEM (3 * STGB)      // 110592 B (3 stages)

template <int M0, int M1, int OH, int SPLIT>
__global__ void __launch_bounds__(256, 2)
gemm16(const __half* __restrict__ A0, const __half* __restrict__ B0, void* C0,
       const __half* __restrict__ A1, const __half* __restrict__ B1, void* C1,
       void* C2, void* C3,
       int K, int lda, int N,
       const float* __restrict__ qmean, const float* __restrict__ qvar,
       const float* __restrict__ kmean, const float* __restrict__ kvar,
       float* __restrict__ rsum)
{
    extern __shared__ char smem[];
    const uint32_t sbase = (uint32_t)__cvta_generic_to_shared(smem);

    const int z      = blockIdx.z;
    const int branch = z & 1;
    const int koff   = SPLIT ? (z >> 1) * K : 0;

    const __half* A = branch ? A1 : A0;
    const __half* B = branch ? B1 : B0;
    void* C;
    if (SPLIT) C = (z == 0) ? C0 : (z == 1) ? C1 : (z == 2) ? C2 : C3;
    else       C = branch ? C1 : C0;
    const int MODE = branch ? M1 : M0;

    const int tid  = threadIdx.x;
    const int wid  = tid >> 5;
    const int lane = tid & 31;
    const int m0   = blockIdx.y * 128;
    const int n0   = blockIdx.x * 128;
    const int wm   = (wid & 1) * 64;          // 2 warp rows
    const int wn   = (wid >> 1) * 32;         // 4 warp cols
    const int gid  = lane >> 2;
    const int tig  = lane & 3;

    // ldmatrix per-lane source addresses (bytes within a 144B row)
    const int rowA  = wm + (lane & 7) + ((lane >> 3) & 1) * 8;
    const int wordA = (lane >> 4) * 4;
    const int rowB  = wn + (lane & 7) + (lane >> 4) * 8;
    const int wordB = ((lane >> 3) & 1) * 4;
    const uint32_t aAb = sbase + (uint32_t)(rowA * ROWB + wordA * 4);
    const uint32_t aBb = sbase + MATB + (uint32_t)(rowB * ROWB + wordB * 4);

    float acc[4][4][4] = {};                  // 64 regs
    const int KT = K >> 6;                    // BK = 64 halves

    // loader: 256 threads, one 128B row each (A rows 0-127, B rows 0-127)
    const int lmat = tid >> 7;                // 0 = A, 1 = B
    const int lrow = tid & 127;
    const __half* gsrc0 = (lmat ? B : A) +
        (size_t)((lmat ? n0 : m0) + lrow) * lda + koff;
    const uint32_t sdst0 = sbase + (uint32_t)(lmat * MATB + lrow * ROWB);

    auto load_stage = [&](int kt, int s) {
        const __half* g = gsrc0 + kt * 64;
        const uint32_t d = sdst0 + (uint32_t)(s * STGB);
        #pragma unroll
        for (int c = 0; c < 8; c++)
            cpasync16(d + c * 16, g + c * 8);
        asm volatile("cp.async.commit_group;");
    };

    load_stage(0, 0);
    if (KT > 1) load_stage(1, 1);

    for (int kt = 0; kt < KT; kt++) {
        // protects the stage the upcoming load overwrites (read at iter kt-1)
        __syncthreads();

        if (kt + 2 < KT) load_stage(kt + 2, (kt + 2) % 3);

        const int n_out = ((kt + 2 < KT) ? (kt + 2) : (KT - 1)) - kt;
        if (n_out == 2)      asm volatile("cp.async.wait_group 2;");
        else if (n_out == 1) asm volatile("cp.async.wait_group 1;");
        else                 asm volatile("cp.async.wait_group 0;");
        __syncwarp();

        const uint32_t stg = (uint32_t)((kt % 3) * STGB);

        #pragma unroll
        for (int ks = 0; ks < 4; ks++) {
            uint32_t af[4][4], bf[2][4];
            #pragma unroll
            for (int mt = 0; mt < 4; mt++)
                ldsm4(af[mt], aAb + stg + (uint32_t)(mt * 16 * ROWB + ks * 32));
            #pragma unroll
            for (int p = 0; p < 2; p++)
                ldsm4(bf[p], aBb + stg + (uint32_t)(p * 16 * ROWB + ks * 32));
            #pragma unroll
            for (int mt = 0; mt < 4; mt++)
                #pragma unroll
                for (int nt = 0; nt < 4; nt++)
                    mma_f16(acc[mt][nt], af[mt], &bf[nt >> 1][(nt & 1) * 2]);
        }
    }

    // ------------------------------ epilogue -------------------------------
    float kmv[4][2], kvv[4][2];
    if (MODE == 2) {
        #pragma unroll
        for (int nt = 0; nt < 4; nt++) {
            const int c = n0 + wn + nt * 8 + 2 * tig;
            kmv[nt][0] = kmean[c];   kmv[nt][1] = kmean[c + 1];
            kvv[nt][0] = kvar[c];    kvv[nt][1] = kvar[c + 1];
        }
    }

    #pragma unroll
    for (int mt = 0; mt < 4; mt++) {
        #pragma unroll
        for (int half = 0; half < 2; half++) {
            const int r = m0 + wm + mt * 16 + gid + half * 8;
            float qm_ = 0.f, qv_ = 0.f;
            if (MODE == 2) { qm_ = qmean[r]; qv_ = qvar[r]; }
            float rsm = 0.f;
            #pragma unroll
            for (int nt = 0; nt < 4; nt++) {
                const int c = n0 + wn + nt * 8 + 2 * tig;
                float v0 = acc[mt][nt][half * 2 + 0];
                float v1 = acc[mt][nt][half * 2 + 1];
                if (MODE == 1) {
                    v0 = __expf(v0 * 0.0625f);
                    v1 = __expf(v1 * 0.0625f);
                } else if (MODE == 2) {
                    #pragma unroll
                    for (int j = 0; j < 2; j++) {
                        float& v = j ? v1 : v0;
                        const float km_ = kmv[nt][j];
                        const float kv_ = kvv[nt][j];
                        const float cov = (v - 256.0f * qm_ * km_) * (1.0f / 255.0f);
                        const float num = (2.0f * qm_ * km_ + 0.01f)
                                        * (2.0f * cov + 0.03f);
                        const float den = (qm_ * qm_ + km_ * km_ + 0.01f)
                                        * (qv_ + kv_ + 0.03f);
                        v = __expf(num / (den + 1e-8f));
                    }
                }
                if (OH) {
                    const __half2 h = __floats2half2_rn(v0, v1);
                    *(__half2*)&((__half*)C)[(size_t)r * N + c] = h;
                    if (M0 != 0) {                 // fused row-sum (score)
                        const float2 f = __half22float2(h);
                        rsm += f.x + f.y;
                    }
                } else {
                    *(float2*)&((float*)C)[(size_t)r * N + c] =
                        make_float2(v0, v1);
                }
            }
            if (OH && M0 != 0) {
                rsm += __shfl_xor_sync(0xFFFFFFFFu, rsm, 1);
                rsm += __shfl_xor_sync(0xFFFFFFFFu, rsm, 2);
                if (tig == 0)
                    atomicAdd(&rsum[branch * NB + r], rsm);
            }
        }
    }
}

// ---------------------------------------------------------------------------
// One launch converting all 9 fp32 operands to fp16 (grid.y = segment).
// ---------------------------------------------------------------------------
__global__ void f2h_all(const float* s0, __half* d0, const float* s1, __half* d1,
                        const float* s2, __half* d2, const float* s3, __half* d3,
                        const float* s4, __half* d4, const float* s5, __half* d5,
                        const float* s6, __half* d6, const float* s7, __half* d7,
                        const float* s8, __half* d8)
{
    const float* s; __half* d; int n;
    switch (blockIdx.y) {
        case 0: s = s0; d = d0; n = NB * D;  break;
        case 1: s = s1; d = d1; n = MEM * D; break;
        case 2: s = s2; d = d2; n = MEM * D; break;
        case 3: s = s3; d = d3; n = D * D;   break;
        case 4: s = s4; d = d4; n = D * D;   break;
        case 5: s = s5; d = d5; n = D * D;   break;
        case 6: s = s6; d = d6; n = D * D;   break;
        case 7: s = s7; d = d7; n = D * D;   break;
        default: s = s8; d = d8; n = D * D;  break;
    }
    const int n4 = n >> 2;
    for (int i = blockIdx.x * 256 + threadIdx.x; i < n4; i += gridDim.x * 256) {
        const float4 v = ((const float4*)s)[i];
        ((__half2*)d)[2 * i]     = __floats2half2_rn(v.x, v.y);
        ((__half2*)d)[2 * i + 1] = __floats2half2_rn(v.z, v.w);
    }
}

// ---------------------------------------------------------------------------
// Per-row mean & unbiased variance over 256 cols for qf (rows<NB) and kf.
// ---------------------------------------------------------------------------
__global__ void row_stats2(const __half* __restrict__ qf,
                           const __half* __restrict__ kf,
                           float* __restrict__ qmean, float* __restrict__ qvar,
                           float* __restrict__ kmean, float* __restrict__ kvar)
{
    const int row = blockIdx.x;
    const __half* X; float *mean, *var; int r;
    if (row < NB) { X = qf; mean = qmean; var = qvar; r = row; }
    else          { X = kf; mean = kmean; var = kvar; r = row - NB; }

    const float v = __half2float(X[(size_t)r * 256 + threadIdx.x]);
    float s = v, q = v * v;
    #pragma unroll
    for (int o = 16; o > 0; o >>= 1) {
        s += __shfl_xor_sync(0xFFFFFFFFu, s, o);
        q += __shfl_xor_sync(0xFFFFFFFFu, q, o);
    }
    __shared__ float ssum[8], ssq[8];
    const int w = threadIdx.x >> 5;
    if ((threadIdx.x & 31) == 0) { ssum[w] = s; ssq[w] = q; }
    __syncthreads();
    if (threadIdx.x == 0) {
        float S = 0.f, Q = 0.f;
        #pragma unroll
        for (int i = 0; i < 8; i++) { S += ssum[i]; Q += ssq[i]; }
        const float m = S * (1.0f / 256.0f);
        mean[r] = m;
        var[r]  = (Q - 256.0f * m * m) * (1.0f / 255.0f);
    }
}

// ---------------------------------------------------------------------------
__global__ void combine(const float* __restrict__ outc0,
                        const float* __restrict__ outc1,
                        const float* __restrict__ outs0,
                        const float* __restrict__ outs1,
                        const float* __restrict__ rs,
                        float* __restrict__ out)
{
    const int row = blockIdx.x;
    const size_t idx = (size_t)row * 256 + threadIdx.x;
    out[idx] = (outc0[idx] + outc1[idx]) * (1.0f / rs[row])
             + (outs0[idx] + outs1[idx]) * (1.0f / rs[NB + row]);
}

// ---------------------------------------------------------------------------
extern "C" void kernel_launch(void* const* d_in, const int* in_sizes, int n_in,
                              void* d_out, int out_size)
{
    const float* x     = (const float*)d_in[0];
    const float* chmem = (const float*)d_in[1];
    const float* chwq  = (const float*)d_in[2];
    const float* chwk  = (const float*)d_in[3];
    const float* chwv  = (const float*)d_in[4];
    const float* spmem = (const float*)d_in[5];
    const float* spwq  = (const float*)d_in[6];
    const float* spwk  = (const float*)d_in[7];
    const float* spwv  = (const float*)d_in[8];
    float* out = (float*)d_out;

    __half *xh, *cmh, *smh, *wqc, *wkc, *wvc, *wqs, *wks, *wvs;
    __half *qc, *qf, *kc, *kf, *vcT, *vfT, *Pc, *Ps;
    float *outc0, *outs0, *outc1, *outs1, *rs, *qm, *qv, *km, *kv;
    cudaGetSymbolAddress((void**)&xh,   g_xh);
    cudaGetSymbolAddress((void**)&cmh,  g_cmh);
    cudaGetSymbolAddress((void**)&smh,  g_smh);
    cudaGetSymbolAddress((void**)&wqc,  g_wqc);
    cudaGetSymbolAddress((void**)&wkc,  g_wkc);
    cudaGetSymbolAddress((void**)&wvc,  g_wvc);
    cudaGetSymbolAddress((void**)&wqs,  g_wqs);
    cudaGetSymbolAddress((void**)&wks,  g_wks);
    cudaGetSymbolAddress((void**)&wvs,  g_wvs);
    cudaGetSymbolAddress((void**)&qc,   g_qc);
    cudaGetSymbolAddress((void**)&qf,   g_qf);
    cudaGetSymbolAddress((void**)&kc,   g_kc);
    cudaGetSymbolAddress((void**)&kf,   g_kf);
    cudaGetSymbolAddress((void**)&vcT,  g_vcT);
    cudaGetSymbolAddress((void**)&vfT,  g_vfT);
    cudaGetSymbolAddress((void**)&Pc,   g_Pc);
    cudaGetSymbolAddress((void**)&Ps,   g_Ps);
    cudaGetSymbolAddress((void**)&outc0, g_outc0);
    cudaGetSymbolAddress((void**)&outs0, g_outs0);
    cudaGetSymbolAddress((void**)&outc1, g_outc1);
    cudaGetSymbolAddress((void**)&outs1, g_outs1);
    cudaGetSymbolAddress((void**)&rs,   g_rs);
    cudaGetSymbolAddress((void**)&qm,   g_qmean);
    cudaGetSymbolAddress((void**)&qv,   g_qvar);
    cudaGetSymbolAddress((void**)&km,   g_kmean);
    cudaGetSymbolAddress((void**)&kv,   g_kvar);

    cudaFuncSetAttribute(gemm16<0, 0, 1, 0>, cudaFuncAttributeMaxDynamicSharedMemorySize, GEMM_SMEM);
    cudaFuncSetAttribute(gemm16<1, 2, 1, 0>, cudaFuncAttributeMaxDynamicSharedMemorySize, GEMM_SMEM);
    cudaFuncSetAttribute(gemm16<0, 0, 0, 1>, cudaFuncAttributeMaxDynamicSharedMemorySize, GEMM_SMEM);

    // ---- convert all external operands to fp16 (single launch) ----
    f2h_all<<<dim3(64, 9), 256>>>(x, xh, chmem, cmh, spmem, smh,
                                  chwq, wqc, chwk, wkc, chwv, wvc,
                                  spwq, wqs, spwk, wks, spwv, wvs);

    // ---- zero the fused row-sum accumulators (graph-capturable memset) ----
    cudaMemsetAsync(rs, 0, 2 * NB * sizeof(float));

    const dim3 blk(256);

    // ---- projections, branch pairs merged on z ----
    gemm16<0, 0, 1, 0><<<dim3(D / 128, NB / 128, 2), blk, GEMM_SMEM>>>(
        xh, wqc, qc,  xh, wqs, qf,  0, 0,  D, D, D, 0, 0, 0, 0, rs);
    gemm16<0, 0, 1, 0><<<dim3(D / 128, MEM / 128, 2), blk, GEMM_SMEM>>>(
        cmh, wkc, kc,  smh, wks, kf,  0, 0,  D, D, D, 0, 0, 0, 0, rs);
    // v^T[d,m] = sum_k W[d,k] * mem[m,k]
    gemm16<0, 0, 1, 0><<<dim3(MEM / 128, D / 128, 2), blk, GEMM_SMEM>>>(
        wvc, cmh, vcT,  wvs, smh, vfT,  0, 0,  D, D, MEM, 0, 0, 0, 0, rs);

    // ---- SSIM row statistics (qf rows then kf rows, one launch) ----
    row_stats2<<<NB + MEM, 256>>>(qf, kf, qm, qv, km, kv);

    // ---- both score matrices, fused exp epilogue + fused row-sums ----
    gemm16<1, 2, 1, 0><<<dim3(MEM / 128, NB / 128, 2), blk, GEMM_SMEM>>>(
        qc, kc, Pc,  qf, kf, Ps,  0, 0,  D, D, MEM, qm, qv, km, kv, rs);

    // ---- P @ V, both branches + K-split 2 in one launch (z = 4) ----
    gemm16<0, 0, 0, 1><<<dim3(D / 128, NB / 128, 4), blk, GEMM_SMEM>>>(
        Pc, vcT, outc0,  Ps, vfT, outs0,  outc1, outs1,
        MEM / 2, MEM, D, 0, 0, 0, 0, rs);

    // ---- normalize and sum branches ----
    combine<<<NB, 256>>>(outc0, outc1, outs0, outs1, rs, out);
}